// round 10
// baseline (speedup 1.0000x reference)
#include <cuda_runtime.h>
#include <math_constants.h>
#include <stdint.h>

#define B_ 2
#define T_ 192
#define C_ 512
#define H_ 8
#define HS_ 64
#define ORDER_ 3
#define BH_ (B_*H_)

#define ITILE_ 12
#define NTHR_ 512

// ---- attn smem float offsets ----
#define OFF_K1B  0                      // [192][40] u32 bf16x2 pair-permuted
#define OFF_K2F  7680                   // [192][40] u32 bf16x2 pair-permuted
#define OFF_V2F  15360                  // [64][104] u32 bf16x2 transposed+permuted
#define OFF_V1S  22016                  // [192][72] fp32 (64 data + pad)
#define OFF_QS   35840                  // [12][64]
#define OFF_YS   36608                  // [2][16][64]
#define OFF_RED  38656                  // [32]
#define OFF_SCR  38688                  // [192][68] staging scratch
#define SMEM_FLOATS 51744               // 206976 B

// ---- proj smem (dynamic): xsP [96][36] float2 + wsP [64][36] float2 ----
#define PJS_ 36
#define PJ_NTHR_ 256
#define PROJ_SMEM_BYTES ((96*PJS_ + 64*PJS_) * 8)

// ---- device scratch ----
__device__ float g_Q [BH_*T_*HS_];
__device__ float g_K1[BH_*T_*HS_];
__device__ float g_K2[BH_*T_*HS_];
__device__ float g_V1[BH_*T_*HS_];
__device__ float g_V2[BH_*T_*HS_];
__device__ float g_Y [B_*T_*C_];

typedef unsigned long long u64;

__device__ __forceinline__ u64 ffma2(u64 a, u64 b, u64 c) {
    u64 d;
    asm("fma.rn.f32x2 %0, %1, %2, %3;" : "=l"(d) : "l"(a), "l"(b), "l"(c));
    return d;
}
__device__ __forceinline__ float pk_sum(u64 v) {
    float lo, hi;
    asm("mov.b64 {%0, %1}, %2;" : "=f"(lo), "=f"(hi) : "l"(v));
    return lo + hi;
}
__device__ __forceinline__ uint32_t bf2(float lo, float hi) {
    uint32_t r;
    asm("cvt.rn.bf16x2.f32 %0, %1, %2;" : "=r"(r) : "f"(hi), "f"(lo));
    return r;
}
__device__ __forceinline__ uint32_t mulbf2(uint32_t a, uint32_t b) {
    uint32_t r;
    asm("mul.bf16x2 %0, %1, %2;" : "=r"(r) : "r"(a), "r"(b));
    return r;
}
__device__ __forceinline__ float ex2f(float x) {
    float r;
    asm("ex2.approx.f32 %0, %1;" : "=f"(r) : "f"(x));
    return r;
}
__device__ __forceinline__ float f2tf(float f) {
    uint32_t r;
    asm("cvt.rna.tf32.f32 %0, %1;" : "=r"(r) : "f"(f));
    return __uint_as_float(r);
}
__device__ __forceinline__ void mma_bf16(float* c,
    uint32_t a0, uint32_t a1, uint32_t a2, uint32_t a3,
    uint32_t b0, uint32_t b1)
{
    asm volatile("mma.sync.aligned.m16n8k16.row.col.f32.bf16.bf16.f32 "
        "{%0,%1,%2,%3}, {%4,%5,%6,%7}, {%8,%9}, {%0,%1,%2,%3};"
        : "+f"(c[0]), "+f"(c[1]), "+f"(c[2]), "+f"(c[3])
        : "r"(a0), "r"(a1), "r"(a2), "r"(a3), "r"(b0), "r"(b1));
}
__device__ __forceinline__ void mma_tf32(float* c,
    uint32_t a0, uint32_t a1, uint32_t a2, uint32_t a3,
    uint32_t b0, uint32_t b1)
{
    asm volatile("mma.sync.aligned.m16n8k8.row.col.f32.tf32.tf32.f32 "
        "{%0,%1,%2,%3}, {%4,%5,%6,%7}, {%8,%9}, {%0,%1,%2,%3};"
        : "+f"(c[0]), "+f"(c[1]), "+f"(c[2]), "+f"(c[3])
        : "r"(a0), "r"(a1), "r"(a2), "r"(a3), "r"(b0), "r"(b1));
}
__device__ __forceinline__ float warpSum(float v) {
#pragma unroll
    for (int o = 16; o; o >>= 1) v += __shfl_xor_sync(0xffffffffu, v, o);
    return v;
}

// =====================================================================
// Kernel 1: projections on tf32 tensor cores.
// grid (BH, 5, 2), block 256. Each CTA: 96 rows x 64 cols x 512 k.
// =====================================================================
__global__ void __launch_bounds__(PJ_NTHR_, 2) proj_kernel(
    const float* __restrict__ x0, const float* __restrict__ x1,
    const float* __restrict__ x2,
    const float* __restrict__ qw, const float* __restrict__ qb,
    const float* __restrict__ kw, const float* __restrict__ kb,
    const float* __restrict__ vw, const float* __restrict__ vb)
{
    extern __shared__ float2 smp[];
    float2* xsP = smp;                 // [96][36]
    float2* wsP = smp + 96*PJS_;       // [64][36]

    int bh = blockIdx.x;
    int m  = blockIdx.y;
    int z  = blockIdx.z;               // row half
    int b  = bh >> 3, h = bh & 7;
    int r0 = z * 96;

    const float* x; const float* w; const float* bias; float* out; int o;
    switch (m) {
        case 0:  x = x0; w = qw; bias = qb; out = g_Q;  o = 0; break;
        case 1:  x = x1; w = kw; bias = kb; out = g_K1; o = 1; break;
        case 2:  x = x2; w = kw; bias = kb; out = g_K2; o = 2; break;
        case 3:  x = x1; w = vw; bias = vb; out = g_V1; o = 1; break;
        default: x = x2; w = vw; bias = vb; out = g_V2; o = 2; break;
    }
    const float* wrow = w + (size_t)(h*ORDER_ + o)*HS_*C_;
    const float* brow = bias + (h*ORDER_ + o)*HS_;
    const float* xrow = x + (size_t)b*T_*C_ + (size_t)r0*C_;

    int tid = threadIdx.x;
    int lane = tid & 31, wid = tid >> 5;
    int g = lane >> 2, t = lane & 3;
    int mt = wid & 1;     // 2 m-tiles of 48 rows
    int ng = wid >> 1;    // 4 col blocks of 16

    float acc[3][2][4] = {};

    for (int kc = 0; kc < 8; ++kc) {
        int cc = kc * 64;
        for (int idx = tid; idx < 96*8; idx += PJ_NTHR_) {
            int r = idx >> 3, sg = idx & 7;
            const float* src = xrow + (size_t)r*C_ + cc + sg*8;
            float4 lo = *(const float4*)src;
            float4 hi = *(const float4*)(src + 4);
            float2* d = &xsP[r*PJS_ + sg*4];
            d[0] = make_float2(f2tf(lo.x), f2tf(hi.x));
            d[1] = make_float2(f2tf(lo.y), f2tf(hi.y));
            d[2] = make_float2(f2tf(lo.z), f2tf(hi.z));
            d[3] = make_float2(f2tf(lo.w), f2tf(hi.w));
        }
        for (int idx = tid; idx < 64*8; idx += PJ_NTHR_) {
            int r = idx >> 3, sg = idx & 7;
            const float* src = wrow + (size_t)r*C_ + cc + sg*8;
            float4 lo = *(const float4*)src;
            float4 hi = *(const float4*)(src + 4);
            float2* d = &wsP[r*PJS_ + sg*4];
            d[0] = make_float2(f2tf(lo.x), f2tf(hi.x));
            d[1] = make_float2(f2tf(lo.y), f2tf(hi.y));
            d[2] = make_float2(f2tf(lo.z), f2tf(hi.z));
            d[3] = make_float2(f2tf(lo.w), f2tf(hi.w));
        }
        __syncthreads();

#pragma unroll
        for (int kk = 0; kk < 8; ++kk) {
            uint32_t b0[2], b1[2];
#pragma unroll
            for (int u = 0; u < 2; ++u) {
                float2 bb = wsP[(ng*16 + u*8 + g)*PJS_ + kk*4 + t];
                b0[u] = __float_as_uint(bb.x);
                b1[u] = __float_as_uint(bb.y);
            }
#pragma unroll
            for (int s = 0; s < 3; ++s) {
                int row = mt*48 + s*16 + g;
                float2 a02 = xsP[row*PJS_ + kk*4 + t];
                float2 a13 = xsP[(row+8)*PJS_ + kk*4 + t];
#pragma unroll
                for (int u = 0; u < 2; ++u)
                    mma_tf32(acc[s][u],
                        __float_as_uint(a02.x), __float_as_uint(a13.x),
                        __float_as_uint(a02.y), __float_as_uint(a13.y),
                        b0[u], b1[u]);
            }
        }
        __syncthreads();
    }

#pragma unroll
    for (int u = 0; u < 2; ++u) {
        int col = ng*16 + u*8 + 2*t;
        float2 bv = *(const float2*)&brow[col];
#pragma unroll
        for (int s = 0; s < 3; ++s) {
            int row = r0 + mt*48 + s*16 + g;
            *(float2*)&out[(size_t)(bh*T_ + row)*HS_ + col] =
                make_float2(acc[s][u][0] + bv.x, acc[s][u][1] + bv.y);
            *(float2*)&out[(size_t)(bh*T_ + row + 8)*HS_ + col] =
                make_float2(acc[s][u][2] + bv.x, acc[s][u][3] + bv.y);
        }
    }
}

// =====================================================================
// Kernel 2: order-3 attention, bf16 mma, register-resident P,
// n-block-streamed exp (spill-free live set). grid (T/12, BH), block 512.
// Fixed-shift softmax (validated R2-R9).
// =====================================================================
__global__ void __launch_bounds__(NTHR_, 1) attn_kernel()
{
    extern __shared__ float sm[];
    uint32_t* K1b = (uint32_t*)(sm + OFF_K1B);  // [192][40]
    uint32_t* K2f = (uint32_t*)(sm + OFF_K2F);  // [192][40]
    uint32_t* V2f = (uint32_t*)(sm + OFF_V2F);  // [64][104]
    float* V1s = sm + OFF_V1S;                  // [192][72]
    float* qs  = sm + OFF_QS;
    float* Ys  = sm + OFF_YS;                   // [2][16][64]
    float* red = sm + OFF_RED;
    float* scr = sm + OFF_SCR;                  // [192][68]

    int bh  = blockIdx.y;
    int it0 = blockIdx.x * ITILE_;
    int tid  = threadIdx.x;
    int lane = tid & 31, wid = tid >> 5;
    int g = lane >> 2;
    int t = lane & 3;
    int mt = wid & 3;     // 16 j-rows within strip
    int ng = wid >> 2;    // GEMM1 n-block (48) == GEMM2 k-block (48)
    int b = bh >> 3, h = bh & 7;

    const float* K1g = g_K1 + (size_t)bh*T_*HS_;
    const float* K2g = g_K2 + (size_t)bh*T_*HS_;
    const float* V1g = g_V1 + (size_t)bh*T_*HS_;
    const float* V2g = g_V2 + (size_t)bh*T_*HS_;

    // ---- Phase A: V2 -> scratch; K1b/K2f bf16 pair-permuted; V1s; qs ----
    for (int idx = tid; idx < 192*16; idx += NTHR_) {
        int r = idx >> 4, dq = (idx & 15) * 4;
        *(float4*)&scr[r*68 + dq] = ((const float4*)V2g)[idx];
        *(float4*)&V1s[r*72 + dq] = ((const float4*)V1g)[idx];
    }
    for (int task = tid; task < 192*4; task += NTHR_) {
        int r = task >> 2, kk = task & 3;
#pragma unroll
        for (int which = 0; which < 2; ++which) {
            const float* src = which ? K2g : K1g;
            uint32_t* dst = (which ? K2f : K1b) + r*40 + kk*8;
            const float4* s4 = (const float4*)(src + (size_t)r*64 + kk*16);
            float4 e0 = s4[0], e1 = s4[1], e2 = s4[2], e3 = s4[3];
            uint32_t p0 = bf2(e0.x, e0.y), p1 = bf2(e0.z, e0.w);
            uint32_t p2 = bf2(e1.x, e1.y), p3 = bf2(e1.z, e1.w);
            uint32_t p4 = bf2(e2.x, e2.y), p5 = bf2(e2.z, e2.w);
            uint32_t p6 = bf2(e3.x, e3.y), p7 = bf2(e3.z, e3.w);
            *(uint4*)(dst)     = make_uint4(p0, p4, p1, p5);
            *(uint4*)(dst + 4) = make_uint4(p2, p6, p3, p7);
        }
    }
    // q scale: 1/sqrt(64) * log2(e)  (exp via ex2)
    for (int idx = tid; idx < ITILE_*64; idx += NTHR_)
        qs[idx] = g_Q[((size_t)bh*T_ + it0 + (idx >> 6))*HS_ + (idx & 63)]
                  * (0.125f * 1.4426950408889634f);
    __syncthreads();
    // ---- Phase B: V2f = transpose + bf16 + pair-permute ----
    for (int task = tid; task < 64*12; task += NTHR_) {
        int kk = task >> 6, d = task & 63;
        float v[16];
#pragma unroll
        for (int i = 0; i < 16; ++i) v[i] = scr[(kk*16 + i)*68 + d];
        uint32_t p[8];
#pragma unroll
        for (int mm = 0; mm < 8; ++mm) p[mm] = bf2(v[2*mm], v[2*mm+1]);
        uint32_t* dst = V2f + d*104 + kk*8;
        *(uint4*)(dst)     = make_uint4(p[0], p[4], p[1], p[5]);
        *(uint4*)(dst + 4) = make_uint4(p[2], p[6], p[3], p[7]);
    }
    __syncthreads();

    for (int ip = 0; ip < ITILE_/2; ++ip) {
        float l_run[2] = {0.f, 0.f};
        float yl[2][8][2] = {};

        for (int js = 0; js < 3; ++js) {
            int j0 = js * 64;
            int rowA = j0 + mt*16 + g;

            // ---- A fragments for both queries (persistent this strip) ----
            uint32_t A[2][4][4];
#pragma unroll
            for (int kk = 0; kk < 4; ++kk) {
                uint2 k1lo = *(const uint2*)&K1b[rowA*40 + kk*8 + 2*t];
                uint2 k1hi = *(const uint2*)&K1b[(rowA+8)*40 + kk*8 + 2*t];
#pragma unroll
                for (int q = 0; q < 2; ++q) {
                    const float* qrow = qs + (ip*2 + q)*64 + kk*16;
                    float2 qa = *(const float2*)&qrow[2*t];
                    float2 qb2 = *(const float2*)&qrow[8 + 2*t];
                    uint32_t q0 = bf2(qa.x, qa.y);
                    uint32_t q1 = bf2(qb2.x, qb2.y);
                    A[q][kk][0] = mulbf2(k1lo.x, q0);
                    A[q][kk][1] = mulbf2(k1hi.x, q0);
                    A[q][kk][2] = mulbf2(k1lo.y, q1);
                    A[q][kk][3] = mulbf2(k1hi.y, q1);
                }
            }

            // ---- GEMM1 streamed in n-blocks of 16; exp immediately ----
            uint32_t a[2][3][4];
#pragma unroll
            for (int m = 0; m < 3; ++m) {
                float c[2][2][4] = {};
#pragma unroll
                for (int kk = 0; kk < 4; ++kk) {
#pragma unroll
                    for (int s2 = 0; s2 < 2; ++s2) {
                        int nrow = ng*48 + (2*m + s2)*8 + g;
                        uint2 bb = *(const uint2*)&K2f[nrow*40 + kk*8 + 2*t];
                        mma_bf16(c[0][s2], A[0][kk][0], A[0][kk][1],
                                 A[0][kk][2], A[0][kk][3], bb.x, bb.y);
                        mma_bf16(c[1][s2], A[1][kk][0], A[1][kk][1],
                                 A[1][kk][2], A[1][kk][3], bb.x, bb.y);
                    }
                }
#pragma unroll
                for (int q = 0; q < 2; ++q) {
                    float e00 = ex2f(c[q][0][0]), e01 = ex2f(c[q][0][1]);
                    float e02 = ex2f(c[q][0][2]), e03 = ex2f(c[q][0][3]);
                    float e10 = ex2f(c[q][1][0]), e11 = ex2f(c[q][1][1]);
                    float e12 = ex2f(c[q][1][2]), e13 = ex2f(c[q][1][3]);
                    l_run[q] += ((e00 + e01) + (e02 + e03))
                              + ((e10 + e11) + (e12 + e13));
                    a[q][m][0] = bf2(e00, e01);
                    a[q][m][1] = bf2(e02, e03);
                    a[q][m][2] = bf2(e10, e11);
                    a[q][m][3] = bf2(e12, e13);
                }
            }

            // ---- GEMM2: u outer, m inner; V1 once per u; no barrier ----
            int jg0 = j0 + mt*16 + g;
#pragma unroll
            for (int u = 0; u < 8; ++u) {
                float w2[2][4] = {};
#pragma unroll
                for (int m = 0; m < 3; ++m) {
                    uint2 bb = *(const uint2*)&V2f[(u*8 + g)*104 + (ng*3 + m)*8 + 2*t];
                    mma_bf16(w2[0], a[0][m][0], a[0][m][1], a[0][m][2], a[0][m][3], bb.x, bb.y);
                    mma_bf16(w2[1], a[1][m][0], a[1][m][1], a[1][m][2], a[1][m][3], bb.x, bb.y);
                }
                int dc = u*8 + 2*t;
                float2 va = *(const float2*)&V1s[jg0*72 + dc];
                float2 vb = *(const float2*)&V1s[(jg0+8)*72 + dc];
#pragma unroll
                for (int q = 0; q < 2; ++q) {
                    yl[q][u][0] += w2[q][0]*va.x + w2[q][2]*vb.x;
                    yl[q][u][1] += w2[q][1]*va.y + w2[q][3]*vb.y;
                }
            }
        }

        // ---- per-query reductions (sum over g via shfl, then 16 warps) ----
#pragma unroll
        for (int q = 0; q < 2; ++q) {
#pragma unroll
            for (int u = 0; u < 8; ++u)
#pragma unroll
                for (int c = 0; c < 2; ++c) {
                    yl[q][u][c] += __shfl_xor_sync(0xffffffffu, yl[q][u][c], 4);
                    yl[q][u][c] += __shfl_xor_sync(0xffffffffu, yl[q][u][c], 8);
                    yl[q][u][c] += __shfl_xor_sync(0xffffffffu, yl[q][u][c], 16);
                }
            float lw = warpSum(l_run[q]);
            if (lane == 0) red[q*16 + wid] = lw;
            if (lane < 4) {
#pragma unroll
                for (int u = 0; u < 8; ++u) {
                    Ys[q*1024 + wid*64 + u*8 + 2*lane + 0] = yl[q][u][0];
                    Ys[q*1024 + wid*64 + u*8 + 2*lane + 1] = yl[q][u][1];
                }
            }
        }
        __syncthreads();
        if (tid < 128) {
            int q = tid >> 6, c64 = tid & 63;
            float lt = 0.f;
#pragma unroll
            for (int w = 0; w < 16; ++w) lt += red[q*16 + w];
            float y = 0.f;
#pragma unroll
            for (int w = 0; w < 16; ++w) y += Ys[q*1024 + w*64 + c64];
            g_Y[((size_t)(b*T_ + it0 + ip*2 + q)*H_ + h)*HS_ + c64] = y / lt;
        }
        __syncthreads();
    }
}

// =====================================================================
// Kernel 3: output projection  out = Y @ cw^T + cb
// =====================================================================
__global__ void outproj_kernel(const float* __restrict__ cw, const float* __restrict__ cb,
                               float* __restrict__ out)
{
    __shared__ float xs[8][64];
    __shared__ float ws[128][68];

    int r0  = blockIdx.x * 8;
    int co0 = blockIdx.y * 128;
    int tid = threadIdx.x;
    int col = tid & 127;
    int rb  = (tid >> 7) * 4;
    u64 acc2[4] = {0ull, 0ull, 0ull, 0ull};

    for (int cc = 0; cc < C_; cc += 64) {
        for (int idx = tid; idx < 8*64; idx += 256) {
            int r = idx >> 6, c = idx & 63;
            xs[r][c] = g_Y[(size_t)(r0 + r)*C_ + cc + c];
        }
        for (int idx = tid; idx < 128*64; idx += 256) {
            int dr = idx >> 6, c = idx & 63;
            ws[dr][c] = cw[(size_t)(co0 + dr)*C_ + cc + c];
        }
        __syncthreads();
        const ulonglong2* wsr = (const ulonglong2*)&ws[col][0];
#pragma unroll
        for (int c4 = 0; c4 < 16; ++c4) {
            ulonglong2 wv = wsr[c4];
#pragma unroll
            for (int r = 0; r < 4; ++r) {
                ulonglong2 xv = *(const ulonglong2*)&xs[rb+r][c4*4];
                acc2[r] = ffma2(xv.x, wv.x, ffma2(xv.y, wv.y, acc2[r]));
            }
        }
        __syncthreads();
    }
    float bv = cb[co0 + col];
#pragma unroll
    for (int rr = 0; rr < 4; ++rr)
        out[(size_t)(r0 + rb + rr)*C_ + co0 + col] = pk_sum(acc2[rr]) + bv;
}

// =====================================================================
extern "C" void kernel_launch(void* const* d_in, const int* in_sizes, int n_in,
                              void* d_out, int out_size)
{
    const float* x0 = (const float*)d_in[0];
    const float* x1 = (const float*)d_in[1];
    const float* x2 = (const float*)d_in[2];
    const float* qw = (const float*)d_in[3];
    const float* qb = (const float*)d_in[4];
    const float* kw = (const float*)d_in[5];
    const float* kb = (const float*)d_in[6];
    const float* vw = (const float*)d_in[7];
    const float* vb = (const float*)d_in[8];
    const float* cw = (const float*)d_in[9];
    const float* cb = (const float*)d_in[10];
    float* out = (float*)d_out;

    cudaFuncSetAttribute(proj_kernel, cudaFuncAttributeMaxDynamicSharedMemorySize,
                         PROJ_SMEM_BYTES);
    proj_kernel<<<dim3(BH_, 5, 2), PJ_NTHR_, PROJ_SMEM_BYTES>>>(
        x0, x1, x2, qw, qb, kw, kb, vw, vb);

    size_t smem = (size_t)SMEM_FLOATS * sizeof(float);
    cudaFuncSetAttribute(attn_kernel, cudaFuncAttributeMaxDynamicSharedMemorySize, (int)smem);
    attn_kernel<<<dim3(T_/ITILE_, BH_), NTHR_, smem>>>();

    outproj_kernel<<<dim3((B_*T_)/8, C_/128), 256>>>(cw, cb, out);
}

// round 11
// speedup vs baseline: 1.1386x; 1.1386x over previous
#include <cuda_runtime.h>
#include <math_constants.h>
#include <stdint.h>

#define B_ 2
#define T_ 192
#define C_ 512
#define H_ 8
#define HS_ 64
#define ORDER_ 3
#define BH_ (B_*H_)

#define ITILE_ 12
#define NTHR_ 512

// ---- attn smem float offsets ----
#define OFF_K1B  0                      // [192][40] u32 bf16x2 pair-permuted
#define OFF_K2F  7680                   // [192][40] u32 bf16x2 pair-permuted
#define OFF_V2F  15360                  // [64][104] u32 bf16x2 transposed+permuted
#define OFF_V1S  22016                  // [192][72] fp32 (64 data + pad)
#define OFF_QS   35840                  // [12][64]
#define OFF_YS   36608                  // [2][16][64]
#define OFF_RED  38656                  // [32]
#define OFF_SCR  38688                  // [192][68] staging scratch
#define SMEM_FLOATS 51744               // 206976 B

// ---- GEMM kernels: pair-permuted tf32 staging, stride 36 float2 ----
#define PJS_ 36
#define PROJ_SMEM_BYTES ((128*PJS_ + 64*PJS_) * 8)
#define OUTP_SMEM_BYTES ((64*PJS_ + 64*PJS_) * 8)

// ---- device scratch ----
__device__ float g_Q [BH_*T_*HS_];
__device__ float g_K1[BH_*T_*HS_];
__device__ float g_K2[BH_*T_*HS_];
__device__ float g_V1[BH_*T_*HS_];
__device__ float g_V2[BH_*T_*HS_];
__device__ float g_Y [B_*T_*C_];

typedef unsigned long long u64;

__device__ __forceinline__ uint32_t bf2(float lo, float hi) {
    uint32_t r;
    asm("cvt.rn.bf16x2.f32 %0, %1, %2;" : "=r"(r) : "f"(hi), "f"(lo));
    return r;
}
__device__ __forceinline__ uint32_t mulbf2(uint32_t a, uint32_t b) {
    uint32_t r;
    asm("mul.bf16x2 %0, %1, %2;" : "=r"(r) : "r"(a), "r"(b));
    return r;
}
__device__ __forceinline__ float ex2f(float x) {
    float r;
    asm("ex2.approx.f32 %0, %1;" : "=f"(r) : "f"(x));
    return r;
}
__device__ __forceinline__ float f2tf(float f) {
    uint32_t r;
    asm("cvt.rna.tf32.f32 %0, %1;" : "=r"(r) : "f"(f));
    return __uint_as_float(r);
}
__device__ __forceinline__ void mma_bf16(float* c,
    uint32_t a0, uint32_t a1, uint32_t a2, uint32_t a3,
    uint32_t b0, uint32_t b1)
{
    asm volatile("mma.sync.aligned.m16n8k16.row.col.f32.bf16.bf16.f32 "
        "{%0,%1,%2,%3}, {%4,%5,%6,%7}, {%8,%9}, {%0,%1,%2,%3};"
        : "+f"(c[0]), "+f"(c[1]), "+f"(c[2]), "+f"(c[3])
        : "r"(a0), "r"(a1), "r"(a2), "r"(a3), "r"(b0), "r"(b1));
}
__device__ __forceinline__ void mma_tf32(float* c,
    uint32_t a0, uint32_t a1, uint32_t a2, uint32_t a3,
    uint32_t b0, uint32_t b1)
{
    asm volatile("mma.sync.aligned.m16n8k8.row.col.f32.tf32.tf32.f32 "
        "{%0,%1,%2,%3}, {%4,%5,%6,%7}, {%8,%9}, {%0,%1,%2,%3};"
        : "+f"(c[0]), "+f"(c[1]), "+f"(c[2]), "+f"(c[3])
        : "r"(a0), "r"(a1), "r"(a2), "r"(a3), "r"(b0), "r"(b1));
}
__device__ __forceinline__ float warpSum(float v) {
#pragma unroll
    for (int o = 16; o; o >>= 1) v += __shfl_xor_sync(0xffffffffu, v, o);
    return v;
}

// staging helper: 8 consecutive floats -> 4 pair-permuted tf32 float2
__device__ __forceinline__ void stage_tf32_pairs(float2* d, const float* src) {
    float4 lo = *(const float4*)src;
    float4 hi = *(const float4*)(src + 4);
    d[0] = make_float2(f2tf(lo.x), f2tf(hi.x));
    d[1] = make_float2(f2tf(lo.y), f2tf(hi.y));
    d[2] = make_float2(f2tf(lo.z), f2tf(hi.z));
    d[3] = make_float2(f2tf(lo.w), f2tf(hi.w));
}

// =====================================================================
// Kernel 1: per-modality projection as 384x512x512 tf32 GEMM.
// grid (3, 8, 5): 128-row tile, head ct (=64 cols), modality. block 256.
// =====================================================================
__global__ void __launch_bounds__(256, 2) proj_kernel(
    const float* __restrict__ x0, const float* __restrict__ x1,
    const float* __restrict__ x2,
    const float* __restrict__ qw, const float* __restrict__ qb,
    const float* __restrict__ kw, const float* __restrict__ kb,
    const float* __restrict__ vw, const float* __restrict__ vb)
{
    extern __shared__ float2 smp[];
    float2* xsP = smp;                 // [128][36]
    float2* wsP = smp + 128*PJS_;      // [64][36]

    int rt = blockIdx.x;               // 128-row tile
    int h  = blockIdx.y;               // head == 64-col tile
    int m  = blockIdx.z;

    const float* x; const float* w; const float* bias; float* out; int o;
    switch (m) {
        case 0:  x = x0; w = qw; bias = qb; out = g_Q;  o = 0; break;
        case 1:  x = x1; w = kw; bias = kb; out = g_K1; o = 1; break;
        case 2:  x = x2; w = kw; bias = kb; out = g_K2; o = 2; break;
        case 3:  x = x1; w = vw; bias = vb; out = g_V1; o = 1; break;
        default: x = x2; w = vw; bias = vb; out = g_V2; o = 2; break;
    }
    const float* wrow = w + (size_t)(h*ORDER_ + o)*HS_*C_;
    const float* brow = bias + (h*ORDER_ + o)*HS_;

    int tid = threadIdx.x;
    int lane = tid & 31, wid = tid >> 5;
    int g = lane >> 2, t = lane & 3;
    int mw = wid & 3;     // 32-row warp tile
    int nw = wid >> 2;    // 32-col warp tile

    float acc[2][4][4] = {};

    for (int kc = 0; kc < 8; ++kc) {
        int cc = kc * 64;
        for (int idx = tid; idx < 128*8; idx += 256) {
            int r = idx >> 3, sg = idx & 7;
            int rg = rt*128 + r;
            int bb = rg >= T_;
            int tt = rg - bb*T_;
            stage_tf32_pairs(&xsP[r*PJS_ + sg*4],
                             x + ((size_t)bb*T_ + tt)*C_ + cc + sg*8);
        }
        for (int idx = tid; idx < 64*8; idx += 256) {
            int r = idx >> 3, sg = idx & 7;
            stage_tf32_pairs(&wsP[r*PJS_ + sg*4],
                             wrow + (size_t)r*C_ + cc + sg*8);
        }
        __syncthreads();

#pragma unroll
        for (int kk = 0; kk < 8; ++kk) {
            uint32_t b0[4], b1[4];
#pragma unroll
            for (int u = 0; u < 4; ++u) {
                float2 bb = wsP[(nw*32 + u*8 + g)*PJS_ + kk*4 + t];
                b0[u] = __float_as_uint(bb.x);
                b1[u] = __float_as_uint(bb.y);
            }
#pragma unroll
            for (int s = 0; s < 2; ++s) {
                int row = mw*32 + s*16 + g;
                float2 a02 = xsP[row*PJS_ + kk*4 + t];
                float2 a13 = xsP[(row+8)*PJS_ + kk*4 + t];
#pragma unroll
                for (int u = 0; u < 4; ++u)
                    mma_tf32(acc[s][u],
                        __float_as_uint(a02.x), __float_as_uint(a13.x),
                        __float_as_uint(a02.y), __float_as_uint(a13.y),
                        b0[u], b1[u]);
            }
        }
        __syncthreads();
    }

#pragma unroll
    for (int u = 0; u < 4; ++u) {
        int col = nw*32 + u*8 + 2*t;
        float2 bv = *(const float2*)&brow[col];
#pragma unroll
        for (int s = 0; s < 2; ++s) {
#pragma unroll
            for (int half = 0; half < 2; ++half) {
                int rg = rt*128 + mw*32 + s*16 + g + half*8;
                int bb = rg >= T_;
                int tt = rg - bb*T_;
                *(float2*)&out[(size_t)((bb*H_ + h)*T_ + tt)*HS_ + col] =
                    make_float2(acc[s][u][2*half] + bv.x,
                                acc[s][u][2*half+1] + bv.y);
            }
        }
    }
}

// =====================================================================
// Kernel 2: order-3 attention (R9-identical), bf16 mma, register-resident
// P. grid (T/12, BH), block 512. Fixed-shift softmax (validated R2-R10).
// =====================================================================
__global__ void __launch_bounds__(NTHR_, 1) attn_kernel()
{
    extern __shared__ float sm[];
    uint32_t* K1b = (uint32_t*)(sm + OFF_K1B);  // [192][40]
    uint32_t* K2f = (uint32_t*)(sm + OFF_K2F);  // [192][40]
    uint32_t* V2f = (uint32_t*)(sm + OFF_V2F);  // [64][104]
    float* V1s = sm + OFF_V1S;                  // [192][72]
    float* qs  = sm + OFF_QS;
    float* Ys  = sm + OFF_YS;                   // [2][16][64]
    float* red = sm + OFF_RED;
    float* scr = sm + OFF_SCR;                  // [192][68]

    int bh  = blockIdx.y;
    int it0 = blockIdx.x * ITILE_;
    int tid  = threadIdx.x;
    int lane = tid & 31, wid = tid >> 5;
    int g = lane >> 2;
    int t = lane & 3;
    int mt = wid & 3;     // 16 j-rows within strip
    int ng = wid >> 2;    // GEMM1 n-block (48) == GEMM2 k-block (48)
    int b = bh >> 3, h = bh & 7;

    const float* K1g = g_K1 + (size_t)bh*T_*HS_;
    const float* K2g = g_K2 + (size_t)bh*T_*HS_;
    const float* V1g = g_V1 + (size_t)bh*T_*HS_;
    const float* V2g = g_V2 + (size_t)bh*T_*HS_;

    // ---- Phase A: V2 -> scratch; K1b/K2f bf16 pair-permuted; V1s; qs ----
    for (int idx = tid; idx < 192*16; idx += NTHR_) {
        int r = idx >> 4, dq = (idx & 15) * 4;
        *(float4*)&scr[r*68 + dq] = ((const float4*)V2g)[idx];
        *(float4*)&V1s[r*72 + dq] = ((const float4*)V1g)[idx];
    }
    for (int task = tid; task < 192*4; task += NTHR_) {
        int r = task >> 2, kk = task & 3;
#pragma unroll
        for (int which = 0; which < 2; ++which) {
            const float* src = which ? K2g : K1g;
            uint32_t* dst = (which ? K2f : K1b) + r*40 + kk*8;
            const float4* s4 = (const float4*)(src + (size_t)r*64 + kk*16);
            float4 e0 = s4[0], e1 = s4[1], e2 = s4[2], e3 = s4[3];
            uint32_t p0 = bf2(e0.x, e0.y), p1 = bf2(e0.z, e0.w);
            uint32_t p2 = bf2(e1.x, e1.y), p3 = bf2(e1.z, e1.w);
            uint32_t p4 = bf2(e2.x, e2.y), p5 = bf2(e2.z, e2.w);
            uint32_t p6 = bf2(e3.x, e3.y), p7 = bf2(e3.z, e3.w);
            *(uint4*)(dst)     = make_uint4(p0, p4, p1, p5);
            *(uint4*)(dst + 4) = make_uint4(p2, p6, p3, p7);
        }
    }
    // q scale: 1/sqrt(64) * log2(e)  (exp via ex2)
    for (int idx = tid; idx < ITILE_*64; idx += NTHR_)
        qs[idx] = g_Q[((size_t)bh*T_ + it0 + (idx >> 6))*HS_ + (idx & 63)]
                  * (0.125f * 1.4426950408889634f);
    __syncthreads();
    // ---- Phase B: V2f = transpose + bf16 + pair-permute ----
    for (int task = tid; task < 64*12; task += NTHR_) {
        int kk = task >> 6, d = task & 63;
        float v[16];
#pragma unroll
        for (int i = 0; i < 16; ++i) v[i] = scr[(kk*16 + i)*68 + d];
        uint32_t p[8];
#pragma unroll
        for (int mm = 0; mm < 8; ++mm) p[mm] = bf2(v[2*mm], v[2*mm+1]);
        uint32_t* dst = V2f + d*104 + kk*8;
        *(uint4*)(dst)     = make_uint4(p[0], p[4], p[1], p[5]);
        *(uint4*)(dst + 4) = make_uint4(p[2], p[6], p[3], p[7]);
    }
    __syncthreads();

    for (int ip = 0; ip < ITILE_/2; ++ip) {
        uint32_t qp[2][4][2];
#pragma unroll
        for (int q = 0; q < 2; ++q) {
            const float* qrow = qs + (ip*2 + q)*64;
#pragma unroll
            for (int kk = 0; kk < 4; ++kk) {
                float2 qa = *(const float2*)&qrow[kk*16 + 2*t];
                float2 qb = *(const float2*)&qrow[kk*16 + 8 + 2*t];
                qp[q][kk][0] = bf2(qa.x, qa.y);
                qp[q][kk][1] = bf2(qb.x, qb.y);
            }
        }
        float l_run[2] = {0.f, 0.f};
        float yl[2][8][2] = {};

        for (int js = 0; js < 3; ++js) {
            int j0 = js * 64;
            int rowA = j0 + mt*16 + g;

            // ---------------- GEMM1: own 16 j-rows x own 48 k-cols ----------
            float c1[2][6][4] = {};
#pragma unroll
            for (int kk = 0; kk < 4; ++kk) {
                uint2 k1lo = *(const uint2*)&K1b[rowA*40 + kk*8 + 2*t];
                uint2 k1hi = *(const uint2*)&K1b[(rowA+8)*40 + kk*8 + 2*t];
                uint32_t A[2][4];
#pragma unroll
                for (int q = 0; q < 2; ++q) {
                    A[q][0] = mulbf2(k1lo.x, qp[q][kk][0]);
                    A[q][1] = mulbf2(k1hi.x, qp[q][kk][0]);
                    A[q][2] = mulbf2(k1lo.y, qp[q][kk][1]);
                    A[q][3] = mulbf2(k1hi.y, qp[q][kk][1]);
                }
#pragma unroll
                for (int s = 0; s < 6; ++s) {
                    int nrow = ng*48 + s*8 + g;
                    uint2 bb = *(const uint2*)&K2f[nrow*40 + kk*8 + 2*t];
                    mma_bf16(c1[0][s], A[0][0], A[0][1], A[0][2], A[0][3], bb.x, bb.y);
                    mma_bf16(c1[1][s], A[1][0], A[1][1], A[1][2], A[1][3], bb.x, bb.y);
                }
            }

            // --------- exp in registers; C-frags ARE the GEMM2 A-frags ------
            uint32_t a[2][3][4];
#pragma unroll
            for (int q = 0; q < 2; ++q) {
#pragma unroll
                for (int m = 0; m < 3; ++m) {
                    float e00 = ex2f(c1[q][2*m][0]),  e01 = ex2f(c1[q][2*m][1]);
                    float e02 = ex2f(c1[q][2*m][2]),  e03 = ex2f(c1[q][2*m][3]);
                    float e10 = ex2f(c1[q][2*m+1][0]), e11 = ex2f(c1[q][2*m+1][1]);
                    float e12 = ex2f(c1[q][2*m+1][2]), e13 = ex2f(c1[q][2*m+1][3]);
                    l_run[q] += ((e00 + e01) + (e02 + e03))
                              + ((e10 + e11) + (e12 + e13));
                    a[q][m][0] = bf2(e00, e01);
                    a[q][m][1] = bf2(e02, e03);
                    a[q][m][2] = bf2(e10, e11);
                    a[q][m][3] = bf2(e12, e13);
                }
            }

            // ------- GEMM2: k-partial (own 48) x all 64 d; no barrier -------
            int jg0 = j0 + mt*16 + g;
#pragma unroll
            for (int u = 0; u < 8; ++u) {
                float w2[2][4] = {};
#pragma unroll
                for (int m = 0; m < 3; ++m) {
                    uint2 bb = *(const uint2*)&V2f[(u*8 + g)*104 + (ng*3 + m)*8 + 2*t];
                    mma_bf16(w2[0], a[0][m][0], a[0][m][1], a[0][m][2], a[0][m][3], bb.x, bb.y);
                    mma_bf16(w2[1], a[1][m][0], a[1][m][1], a[1][m][2], a[1][m][3], bb.x, bb.y);
                }
                int dc = u*8 + 2*t;
                float2 va = *(const float2*)&V1s[jg0*72 + dc];
                float2 vb = *(const float2*)&V1s[(jg0+8)*72 + dc];
#pragma unroll
                for (int q = 0; q < 2; ++q) {
                    yl[q][u][0] += w2[q][0]*va.x + w2[q][2]*vb.x;
                    yl[q][u][1] += w2[q][1]*va.y + w2[q][3]*vb.y;
                }
            }
        }

        // ---- per-query reductions (sum over g via shfl, then 16 warps) ----
#pragma unroll
        for (int q = 0; q < 2; ++q) {
#pragma unroll
            for (int u = 0; u < 8; ++u)
#pragma unroll
                for (int c = 0; c < 2; ++c) {
                    yl[q][u][c] += __shfl_xor_sync(0xffffffffu, yl[q][u][c], 4);
                    yl[q][u][c] += __shfl_xor_sync(0xffffffffu, yl[q][u][c], 8);
                    yl[q][u][c] += __shfl_xor_sync(0xffffffffu, yl[q][u][c], 16);
                }
            float lw = warpSum(l_run[q]);
            if (lane == 0) red[q*16 + wid] = lw;
            if (lane < 4) {
#pragma unroll
                for (int u = 0; u < 8; ++u) {
                    Ys[q*1024 + wid*64 + u*8 + 2*lane + 0] = yl[q][u][0];
                    Ys[q*1024 + wid*64 + u*8 + 2*lane + 1] = yl[q][u][1];
                }
            }
        }
        __syncthreads();
        if (tid < 128) {
            int q = tid >> 6, c64 = tid & 63;
            float lt = 0.f;
#pragma unroll
            for (int w = 0; w < 16; ++w) lt += red[q*16 + w];
            float y = 0.f;
#pragma unroll
            for (int w = 0; w < 16; ++w) y += Ys[q*1024 + w*64 + c64];
            g_Y[((size_t)(b*T_ + it0 + ip*2 + q)*H_ + h)*HS_ + c64] = y / lt;
        }
        __syncthreads();
    }
}

// =====================================================================
// Kernel 3: output projection as 384x512x512 tf32 GEMM.
// grid (6, 8): 64-row tile x 64-col tile. block 256.
// =====================================================================
__global__ void __launch_bounds__(256, 2) outproj_kernel(
    const float* __restrict__ cw, const float* __restrict__ cb,
    float* __restrict__ out)
{
    extern __shared__ float2 smp[];
    float2* xsP = smp;                 // [64][36]
    float2* wsP = smp + 64*PJS_;       // [64][36]

    int rt  = blockIdx.x;              // 64-row tile
    int ct  = blockIdx.y;              // 64-col tile
    int co0 = ct * 64;

    int tid = threadIdx.x;
    int lane = tid & 31, wid = tid >> 5;
    int g = lane >> 2, t = lane & 3;
    int mw = wid & 1;     // 32-row warp tile
    int nw = wid >> 1;    // 16-col warp tile

    float acc[2][2][4] = {};

    for (int kc = 0; kc < 8; ++kc) {
        int cc = kc * 64;
        for (int idx = tid; idx < 64*8; idx += 256) {
            int r = idx >> 3, sg = idx & 7;
            stage_tf32_pairs(&xsP[r*PJS_ + sg*4],
                             g_Y + (size_t)(rt*64 + r)*C_ + cc + sg*8);
        }
        for (int idx = tid; idx < 64*8; idx += 256) {
            int r = idx >> 3, sg = idx & 7;
            stage_tf32_pairs(&wsP[r*PJS_ + sg*4],
                             cw + (size_t)(co0 + r)*C_ + cc + sg*8);
        }
        __syncthreads();

#pragma unroll
        for (int kk = 0; kk < 8; ++kk) {
            uint32_t b0[2], b1[2];
#pragma unroll
            for (int u = 0; u < 2; ++u) {
                float2 bb = wsP[(nw*16 + u*8 + g)*PJS_ + kk*4 + t];
                b0[u] = __float_as_uint(bb.x);
                b1[u] = __float_as_uint(bb.y);
            }
#pragma unroll
            for (int s = 0; s < 2; ++s) {
                int row = mw*32 + s*16 + g;
                float2 a02 = xsP[row*PJS_ + kk*4 + t];
                float2 a13 = xsP[(row+8)*PJS_ + kk*4 + t];
#pragma unroll
                for (int u = 0; u < 2; ++u)
                    mma_tf32(acc[s][u],
                        __float_as_uint(a02.x), __float_as_uint(a13.x),
                        __float_as_uint(a02.y), __float_as_uint(a13.y),
                        b0[u], b1[u]);
            }
        }
        __syncthreads();
    }

#pragma unroll
    for (int u = 0; u < 2; ++u) {
        int col = co0 + nw*16 + u*8 + 2*t;
        float2 bv = *(const float2*)&cb[col];
#pragma unroll
        for (int s = 0; s < 2; ++s) {
            int rg = rt*64 + mw*32 + s*16 + g;
            *(float2*)&out[(size_t)rg*C_ + col] =
                make_float2(acc[s][u][0] + bv.x, acc[s][u][1] + bv.y);
            *(float2*)&out[(size_t)(rg+8)*C_ + col] =
                make_float2(acc[s][u][2] + bv.x, acc[s][u][3] + bv.y);
        }
    }
}

// =====================================================================
extern "C" void kernel_launch(void* const* d_in, const int* in_sizes, int n_in,
                              void* d_out, int out_size)
{
    const float* x0 = (const float*)d_in[0];
    const float* x1 = (const float*)d_in[1];
    const float* x2 = (const float*)d_in[2];
    const float* qw = (const float*)d_in[3];
    const float* qb = (const float*)d_in[4];
    const float* kw = (const float*)d_in[5];
    const float* kb = (const float*)d_in[6];
    const float* vw = (const float*)d_in[7];
    const float* vb = (const float*)d_in[8];
    const float* cw = (const float*)d_in[9];
    const float* cb = (const float*)d_in[10];
    float* out = (float*)d_out;

    cudaFuncSetAttribute(proj_kernel, cudaFuncAttributeMaxDynamicSharedMemorySize,
                         PROJ_SMEM_BYTES);
    proj_kernel<<<dim3(3, H_, 5), 256, PROJ_SMEM_BYTES>>>(
        x0, x1, x2, qw, qb, kw, kb, vw, vb);

    size_t smem = (size_t)SMEM_FLOATS * sizeof(float);
    cudaFuncSetAttribute(attn_kernel, cudaFuncAttributeMaxDynamicSharedMemorySize, (int)smem);
    attn_kernel<<<dim3(T_/ITILE_, BH_), NTHR_, smem>>>();

    cudaFuncSetAttribute(outproj_kernel, cudaFuncAttributeMaxDynamicSharedMemorySize,
                         OUTP_SMEM_BYTES);
    outproj_kernel<<<dim3(6, 8), 256, OUTP_SMEM_BYTES>>>(cw, cb, out);
}

// round 12
// speedup vs baseline: 1.2031x; 1.0566x over previous
#include <cuda_runtime.h>
#include <math_constants.h>
#include <stdint.h>

#define B_ 2
#define T_ 192
#define C_ 512
#define H_ 8
#define HS_ 64
#define ORDER_ 3
#define BH_ (B_*H_)

#define ITILE_ 12
#define NTHR_ 512

// ---- attn smem float offsets ----
#define OFF_K1B  0                      // [192][40] u32 bf16x2 pair-permuted
#define OFF_K2F  7680                   // [192][40] u32 bf16x2 pair-permuted
#define OFF_V2F  15360                  // [64][104] u32 bf16x2 transposed+permuted
#define OFF_V1S  22016                  // [192][72] fp32 (64 data + pad)
#define OFF_QS   35840                  // [12][64]
#define OFF_YS   36608                  // [2][16][64]
#define OFF_RED  38656                  // [32]
#define OFF_SCR  38688                  // [192][68] staging scratch
#define SMEM_FLOATS 51744               // 206976 B

// ---- GEMM kernels: pair-permuted tf32 staging, stride 36 float2 ----
#define PJS_ 36
#define PROJ_BUF_F2   (128*PJS_ + 64*PJS_)          // one buffer (float2)
#define PROJ_SMEM_BYTES (2 * PROJ_BUF_F2 * 8)       // 110592 B
#define OUTP_BUF_F2   (64*PJS_ + 64*PJS_)
#define OUTP_SMEM_BYTES (2 * OUTP_BUF_F2 * 8)       // 73728 B

// ---- device scratch ----
__device__ float g_Q [BH_*T_*HS_];
__device__ float g_K1[BH_*T_*HS_];
__device__ float g_K2[BH_*T_*HS_];
__device__ float g_V1[BH_*T_*HS_];
__device__ float g_V2[BH_*T_*HS_];
__device__ float g_Y [B_*T_*C_];

typedef unsigned long long u64;

__device__ __forceinline__ uint32_t bf2(float lo, float hi) {
    uint32_t r;
    asm("cvt.rn.bf16x2.f32 %0, %1, %2;" : "=r"(r) : "f"(hi), "f"(lo));
    return r;
}
__device__ __forceinline__ uint32_t mulbf2(uint32_t a, uint32_t b) {
    uint32_t r;
    asm("mul.bf16x2 %0, %1, %2;" : "=r"(r) : "r"(a), "r"(b));
    return r;
}
__device__ __forceinline__ float ex2f(float x) {
    float r;
    asm("ex2.approx.f32 %0, %1;" : "=f"(r) : "f"(x));
    return r;
}
__device__ __forceinline__ float f2tf(float f) {
    uint32_t r;
    asm("cvt.rna.tf32.f32 %0, %1;" : "=r"(r) : "f"(f));
    return __uint_as_float(r);
}
__device__ __forceinline__ void mma_bf16(float* c,
    uint32_t a0, uint32_t a1, uint32_t a2, uint32_t a3,
    uint32_t b0, uint32_t b1)
{
    asm volatile("mma.sync.aligned.m16n8k16.row.col.f32.bf16.bf16.f32 "
        "{%0,%1,%2,%3}, {%4,%5,%6,%7}, {%8,%9}, {%0,%1,%2,%3};"
        : "+f"(c[0]), "+f"(c[1]), "+f"(c[2]), "+f"(c[3])
        : "r"(a0), "r"(a1), "r"(a2), "r"(a3), "r"(b0), "r"(b1));
}
__device__ __forceinline__ void mma_tf32(float* c,
    uint32_t a0, uint32_t a1, uint32_t a2, uint32_t a3,
    uint32_t b0, uint32_t b1)
{
    asm volatile("mma.sync.aligned.m16n8k8.row.col.f32.tf32.tf32.f32 "
        "{%0,%1,%2,%3}, {%4,%5,%6,%7}, {%8,%9}, {%0,%1,%2,%3};"
        : "+f"(c[0]), "+f"(c[1]), "+f"(c[2]), "+f"(c[3])
        : "r"(a0), "r"(a1), "r"(a2), "r"(a3), "r"(b0), "r"(b1));
}
__device__ __forceinline__ float warpSum(float v) {
#pragma unroll
    for (int o = 16; o; o >>= 1) v += __shfl_xor_sync(0xffffffffu, v, o);
    return v;
}

// convert 8 floats (lo,hi float4 regs) -> 4 pair-permuted tf32 float2 in smem
__device__ __forceinline__ void store_tf32_pairs(float2* d, float4 lo, float4 hi) {
    d[0] = make_float2(f2tf(lo.x), f2tf(hi.x));
    d[1] = make_float2(f2tf(lo.y), f2tf(hi.y));
    d[2] = make_float2(f2tf(lo.z), f2tf(hi.z));
    d[3] = make_float2(f2tf(lo.w), f2tf(hi.w));
}

// =====================================================================
// Kernel 1: per-modality projection as 384x512x512 tf32 GEMM,
// double-buffered smem + register prefetch (1 barrier / k-chunk).
// grid (3, 8, 5), block 256.
// =====================================================================
__global__ void __launch_bounds__(256) proj_kernel(
    const float* __restrict__ x0, const float* __restrict__ x1,
    const float* __restrict__ x2,
    const float* __restrict__ qw, const float* __restrict__ qb,
    const float* __restrict__ kw, const float* __restrict__ kb,
    const float* __restrict__ vw, const float* __restrict__ vb)
{
    extern __shared__ float2 smp[];

    int rt = blockIdx.x;               // 128-row tile
    int h  = blockIdx.y;               // head == 64-col tile
    int m  = blockIdx.z;

    const float* x; const float* w; const float* bias; float* out; int o;
    switch (m) {
        case 0:  x = x0; w = qw; bias = qb; out = g_Q;  o = 0; break;
        case 1:  x = x1; w = kw; bias = kb; out = g_K1; o = 1; break;
        case 2:  x = x2; w = kw; bias = kb; out = g_K2; o = 2; break;
        case 3:  x = x1; w = vw; bias = vb; out = g_V1; o = 1; break;
        default: x = x2; w = vw; bias = vb; out = g_V2; o = 2; break;
    }
    const float* wrow = w + (size_t)(h*ORDER_ + o)*HS_*C_;
    const float* brow = bias + (h*ORDER_ + o)*HS_;

    int tid = threadIdx.x;
    int lane = tid & 31, wid = tid >> 5;
    int g = lane >> 2, t = lane & 3;
    int mw = wid & 3;     // 32-row warp tile
    int nw = wid >> 2;    // 32-col warp tile

    // per-thread staging assignments (row pointers fixed; cc varies)
    const float* xsrc[4];
    int xdst[4];
#pragma unroll
    for (int k = 0; k < 4; ++k) {
        int idx = tid + k*256;
        int r = idx >> 3, sg = idx & 7;
        int rg = rt*128 + r;
        int bb = rg >= T_;
        int tt = rg - bb*T_;
        xsrc[k] = x + ((size_t)bb*T_ + tt)*C_ + sg*8;
        xdst[k] = r*PJS_ + sg*4;
    }
    const float* wsrc[2];
    int wdst[2];
#pragma unroll
    for (int k = 0; k < 2; ++k) {
        int idx = tid + k*256;
        int r = idx >> 3, sg = idx & 7;
        wsrc[k] = wrow + (size_t)r*C_ + sg*8;
        wdst[k] = 128*PJS_ + r*PJS_ + sg*4;
    }

    float4 pxl[4], pxh[4], pwl[2], pwh[2];
    // preload kc=0
#pragma unroll
    for (int k = 0; k < 4; ++k) {
        pxl[k] = *(const float4*)(xsrc[k]);
        pxh[k] = *(const float4*)(xsrc[k] + 4);
    }
#pragma unroll
    for (int k = 0; k < 2; ++k) {
        pwl[k] = *(const float4*)(wsrc[k]);
        pwh[k] = *(const float4*)(wsrc[k] + 4);
    }
    {
        float2* buf = smp;
#pragma unroll
        for (int k = 0; k < 4; ++k) store_tf32_pairs(&buf[xdst[k]], pxl[k], pxh[k]);
#pragma unroll
        for (int k = 0; k < 2; ++k) store_tf32_pairs(&buf[wdst[k]], pwl[k], pwh[k]);
    }
    __syncthreads();

    float acc[2][4][4] = {};

    for (int kc = 0; kc < 8; ++kc) {
        // prefetch kc+1 (LDGs in flight during compute)
        if (kc < 7) {
            int cc = (kc + 1) * 64;
#pragma unroll
            for (int k = 0; k < 4; ++k) {
                pxl[k] = *(const float4*)(xsrc[k] + cc);
                pxh[k] = *(const float4*)(xsrc[k] + cc + 4);
            }
#pragma unroll
            for (int k = 0; k < 2; ++k) {
                pwl[k] = *(const float4*)(wsrc[k] + cc);
                pwh[k] = *(const float4*)(wsrc[k] + cc + 4);
            }
        }

        const float2* xsP = smp + (kc & 1) * PROJ_BUF_F2;
        const float2* wsP = xsP + 128*PJS_;
#pragma unroll
        for (int kk = 0; kk < 8; ++kk) {
            uint32_t b0[4], b1[4];
#pragma unroll
            for (int u = 0; u < 4; ++u) {
                float2 bb = wsP[(nw*32 + u*8 + g)*PJS_ + kk*4 + t];
                b0[u] = __float_as_uint(bb.x);
                b1[u] = __float_as_uint(bb.y);
            }
#pragma unroll
            for (int s = 0; s < 2; ++s) {
                int row = mw*32 + s*16 + g;
                float2 a02 = xsP[row*PJS_ + kk*4 + t];
                float2 a13 = xsP[(row+8)*PJS_ + kk*4 + t];
#pragma unroll
                for (int u = 0; u < 4; ++u)
                    mma_tf32(acc[s][u],
                        __float_as_uint(a02.x), __float_as_uint(a13.x),
                        __float_as_uint(a02.y), __float_as_uint(a13.y),
                        b0[u], b1[u]);
            }
        }

        if (kc < 7) {
            float2* buf = smp + ((kc + 1) & 1) * PROJ_BUF_F2;
#pragma unroll
            for (int k = 0; k < 4; ++k) store_tf32_pairs(&buf[xdst[k]], pxl[k], pxh[k]);
#pragma unroll
            for (int k = 0; k < 2; ++k) store_tf32_pairs(&buf[wdst[k]], pwl[k], pwh[k]);
            __syncthreads();
        }
    }

#pragma unroll
    for (int u = 0; u < 4; ++u) {
        int col = nw*32 + u*8 + 2*t;
        float2 bv = *(const float2*)&brow[col];
#pragma unroll
        for (int s = 0; s < 2; ++s) {
#pragma unroll
            for (int half = 0; half < 2; ++half) {
                int rg = rt*128 + mw*32 + s*16 + g + half*8;
                int bb = rg >= T_;
                int tt = rg - bb*T_;
                *(float2*)&out[(size_t)((bb*H_ + h)*T_ + tt)*HS_ + col] =
                    make_float2(acc[s][u][2*half] + bv.x,
                                acc[s][u][2*half+1] + bv.y);
            }
        }
    }
}

// =====================================================================
// Kernel 2: order-3 attention (R11-identical), bf16 mma, register-resident
// P. grid (T/12, BH), block 512. Fixed-shift softmax (validated R2-R11).
// =====================================================================
__global__ void __launch_bounds__(NTHR_, 1) attn_kernel()
{
    extern __shared__ float sm[];
    uint32_t* K1b = (uint32_t*)(sm + OFF_K1B);  // [192][40]
    uint32_t* K2f = (uint32_t*)(sm + OFF_K2F);  // [192][40]
    uint32_t* V2f = (uint32_t*)(sm + OFF_V2F);  // [64][104]
    float* V1s = sm + OFF_V1S;                  // [192][72]
    float* qs  = sm + OFF_QS;
    float* Ys  = sm + OFF_YS;                   // [2][16][64]
    float* red = sm + OFF_RED;
    float* scr = sm + OFF_SCR;                  // [192][68]

    int bh  = blockIdx.y;
    int it0 = blockIdx.x * ITILE_;
    int tid  = threadIdx.x;
    int lane = tid & 31, wid = tid >> 5;
    int g = lane >> 2;
    int t = lane & 3;
    int mt = wid & 3;     // 16 j-rows within strip
    int ng = wid >> 2;    // GEMM1 n-block (48) == GEMM2 k-block (48)
    int b = bh >> 3, h = bh & 7;

    const float* K1g = g_K1 + (size_t)bh*T_*HS_;
    const float* K2g = g_K2 + (size_t)bh*T_*HS_;
    const float* V1g = g_V1 + (size_t)bh*T_*HS_;
    const float* V2g = g_V2 + (size_t)bh*T_*HS_;

    // ---- Phase A: V2 -> scratch; K1b/K2f bf16 pair-permuted; V1s; qs ----
    for (int idx = tid; idx < 192*16; idx += NTHR_) {
        int r = idx >> 4, dq = (idx & 15) * 4;
        *(float4*)&scr[r*68 + dq] = ((const float4*)V2g)[idx];
        *(float4*)&V1s[r*72 + dq] = ((const float4*)V1g)[idx];
    }
    for (int task = tid; task < 192*4; task += NTHR_) {
        int r = task >> 2, kk = task & 3;
#pragma unroll
        for (int which = 0; which < 2; ++which) {
            const float* src = which ? K2g : K1g;
            uint32_t* dst = (which ? K2f : K1b) + r*40 + kk*8;
            const float4* s4 = (const float4*)(src + (size_t)r*64 + kk*16);
            float4 e0 = s4[0], e1 = s4[1], e2 = s4[2], e3 = s4[3];
            uint32_t p0 = bf2(e0.x, e0.y), p1 = bf2(e0.z, e0.w);
            uint32_t p2 = bf2(e1.x, e1.y), p3 = bf2(e1.z, e1.w);
            uint32_t p4 = bf2(e2.x, e2.y), p5 = bf2(e2.z, e2.w);
            uint32_t p6 = bf2(e3.x, e3.y), p7 = bf2(e3.z, e3.w);
            *(uint4*)(dst)     = make_uint4(p0, p4, p1, p5);
            *(uint4*)(dst + 4) = make_uint4(p2, p6, p3, p7);
        }
    }
    // q scale: 1/sqrt(64) * log2(e)  (exp via ex2)
    for (int idx = tid; idx < ITILE_*64; idx += NTHR_)
        qs[idx] = g_Q[((size_t)bh*T_ + it0 + (idx >> 6))*HS_ + (idx & 63)]
                  * (0.125f * 1.4426950408889634f);
    __syncthreads();
    // ---- Phase B: V2f = transpose + bf16 + pair-permute ----
    for (int task = tid; task < 64*12; task += NTHR_) {
        int kk = task >> 6, d = task & 63;
        float v[16];
#pragma unroll
        for (int i = 0; i < 16; ++i) v[i] = scr[(kk*16 + i)*68 + d];
        uint32_t p[8];
#pragma unroll
        for (int mm = 0; mm < 8; ++mm) p[mm] = bf2(v[2*mm], v[2*mm+1]);
        uint32_t* dst = V2f + d*104 + kk*8;
        *(uint4*)(dst)     = make_uint4(p[0], p[4], p[1], p[5]);
        *(uint4*)(dst + 4) = make_uint4(p[2], p[6], p[3], p[7]);
    }
    __syncthreads();

    for (int ip = 0; ip < ITILE_/2; ++ip) {
        uint32_t qp[2][4][2];
#pragma unroll
        for (int q = 0; q < 2; ++q) {
            const float* qrow = qs + (ip*2 + q)*64;
#pragma unroll
            for (int kk = 0; kk < 4; ++kk) {
                float2 qa = *(const float2*)&qrow[kk*16 + 2*t];
                float2 qb = *(const float2*)&qrow[kk*16 + 8 + 2*t];
                qp[q][kk][0] = bf2(qa.x, qa.y);
                qp[q][kk][1] = bf2(qb.x, qb.y);
            }
        }
        float l_run[2] = {0.f, 0.f};
        float yl[2][8][2] = {};

        for (int js = 0; js < 3; ++js) {
            int j0 = js * 64;
            int rowA = j0 + mt*16 + g;

            // ---------------- GEMM1: own 16 j-rows x own 48 k-cols ----------
            float c1[2][6][4] = {};
#pragma unroll
            for (int kk = 0; kk < 4; ++kk) {
                uint2 k1lo = *(const uint2*)&K1b[rowA*40 + kk*8 + 2*t];
                uint2 k1hi = *(const uint2*)&K1b[(rowA+8)*40 + kk*8 + 2*t];
                uint32_t A[2][4];
#pragma unroll
                for (int q = 0; q < 2; ++q) {
                    A[q][0] = mulbf2(k1lo.x, qp[q][kk][0]);
                    A[q][1] = mulbf2(k1hi.x, qp[q][kk][0]);
                    A[q][2] = mulbf2(k1lo.y, qp[q][kk][1]);
                    A[q][3] = mulbf2(k1hi.y, qp[q][kk][1]);
                }
#pragma unroll
                for (int s = 0; s < 6; ++s) {
                    int nrow = ng*48 + s*8 + g;
                    uint2 bb = *(const uint2*)&K2f[nrow*40 + kk*8 + 2*t];
                    mma_bf16(c1[0][s], A[0][0], A[0][1], A[0][2], A[0][3], bb.x, bb.y);
                    mma_bf16(c1[1][s], A[1][0], A[1][1], A[1][2], A[1][3], bb.x, bb.y);
                }
            }

            // --------- exp in registers; C-frags ARE the GEMM2 A-frags ------
            uint32_t a[2][3][4];
#pragma unroll
            for (int q = 0; q < 2; ++q) {
#pragma unroll
                for (int m = 0; m < 3; ++m) {
                    float e00 = ex2f(c1[q][2*m][0]),  e01 = ex2f(c1[q][2*m][1]);
                    float e02 = ex2f(c1[q][2*m][2]),  e03 = ex2f(c1[q][2*m][3]);
                    float e10 = ex2f(c1[q][2*m+1][0]), e11 = ex2f(c1[q][2*m+1][1]);
                    float e12 = ex2f(c1[q][2*m+1][2]), e13 = ex2f(c1[q][2*m+1][3]);
                    l_run[q] += ((e00 + e01) + (e02 + e03))
                              + ((e10 + e11) + (e12 + e13));
                    a[q][m][0] = bf2(e00, e01);
                    a[q][m][1] = bf2(e02, e03);
                    a[q][m][2] = bf2(e10, e11);
                    a[q][m][3] = bf2(e12, e13);
                }
            }

            // ------- GEMM2: k-partial (own 48) x all 64 d; no barrier -------
            int jg0 = j0 + mt*16 + g;
#pragma unroll
            for (int u = 0; u < 8; ++u) {
                float w2[2][4] = {};
#pragma unroll
                for (int m = 0; m < 3; ++m) {
                    uint2 bb = *(const uint2*)&V2f[(u*8 + g)*104 + (ng*3 + m)*8 + 2*t];
                    mma_bf16(w2[0], a[0][m][0], a[0][m][1], a[0][m][2], a[0][m][3], bb.x, bb.y);
                    mma_bf16(w2[1], a[1][m][0], a[1][m][1], a[1][m][2], a[1][m][3], bb.x, bb.y);
                }
                int dc = u*8 + 2*t;
                float2 va = *(const float2*)&V1s[jg0*72 + dc];
                float2 vb = *(const float2*)&V1s[(jg0+8)*72 + dc];
#pragma unroll
                for (int q = 0; q < 2; ++q) {
                    yl[q][u][0] += w2[q][0]*va.x + w2[q][2]*vb.x;
                    yl[q][u][1] += w2[q][1]*va.y + w2[q][3]*vb.y;
                }
            }
        }

        // ---- per-query reductions (sum over g via shfl, then 16 warps) ----
#pragma unroll
        for (int q = 0; q < 2; ++q) {
#pragma unroll
            for (int u = 0; u < 8; ++u)
#pragma unroll
                for (int c = 0; c < 2; ++c) {
                    yl[q][u][c] += __shfl_xor_sync(0xffffffffu, yl[q][u][c], 4);
                    yl[q][u][c] += __shfl_xor_sync(0xffffffffu, yl[q][u][c], 8);
                    yl[q][u][c] += __shfl_xor_sync(0xffffffffu, yl[q][u][c], 16);
                }
            float lw = warpSum(l_run[q]);
            if (lane == 0) red[q*16 + wid] = lw;
            if (lane < 4) {
#pragma unroll
                for (int u = 0; u < 8; ++u) {
                    Ys[q*1024 + wid*64 + u*8 + 2*lane + 0] = yl[q][u][0];
                    Ys[q*1024 + wid*64 + u*8 + 2*lane + 1] = yl[q][u][1];
                }
            }
        }
        __syncthreads();
        if (tid < 128) {
            int q = tid >> 6, c64 = tid & 63;
            float lt = 0.f;
#pragma unroll
            for (int w = 0; w < 16; ++w) lt += red[q*16 + w];
            float y = 0.f;
#pragma unroll
            for (int w = 0; w < 16; ++w) y += Ys[q*1024 + w*64 + c64];
            g_Y[((size_t)(b*T_ + it0 + ip*2 + q)*H_ + h)*HS_ + c64] = y / lt;
        }
        __syncthreads();
    }
}

// =====================================================================
// Kernel 3: output projection as 384x512x512 tf32 GEMM, double-buffered.
// grid (6, 8): 64-row tile x 64-col tile. block 256.
// =====================================================================
__global__ void __launch_bounds__(256) outproj_kernel(
    const float* __restrict__ cw, const float* __restrict__ cb,
    float* __restrict__ out)
{
    extern __shared__ float2 smp[];

    int rt  = blockIdx.x;              // 64-row tile
    int ct  = blockIdx.y;              // 64-col tile
    int co0 = ct * 64;

    int tid = threadIdx.x;
    int lane = tid & 31, wid = tid >> 5;
    int g = lane >> 2, t = lane & 3;
    int mw = wid & 1;     // 32-row warp tile
    int nw = wid >> 1;    // 16-col warp tile

    const float* xsrc[2];
    int xdst[2];
    const float* wsrc[2];
    int wdst[2];
#pragma unroll
    for (int k = 0; k < 2; ++k) {
        int idx = tid + k*256;
        int r = idx >> 3, sg = idx & 7;
        xsrc[k] = g_Y + (size_t)(rt*64 + r)*C_ + sg*8;
        xdst[k] = r*PJS_ + sg*4;
        wsrc[k] = cw + (size_t)(co0 + r)*C_ + sg*8;
        wdst[k] = 64*PJS_ + r*PJS_ + sg*4;
    }

    float4 pxl[2], pxh[2], pwl[2], pwh[2];
#pragma unroll
    for (int k = 0; k < 2; ++k) {
        pxl[k] = *(const float4*)(xsrc[k]);
        pxh[k] = *(const float4*)(xsrc[k] + 4);
        pwl[k] = *(const float4*)(wsrc[k]);
        pwh[k] = *(const float4*)(wsrc[k] + 4);
    }
    {
        float2* buf = smp;
#pragma unroll
        for (int k = 0; k < 2; ++k) {
            store_tf32_pairs(&buf[xdst[k]], pxl[k], pxh[k]);
            store_tf32_pairs(&buf[wdst[k]], pwl[k], pwh[k]);
        }
    }
    __syncthreads();

    float acc[2][2][4] = {};

    for (int kc = 0; kc < 8; ++kc) {
        if (kc < 7) {
            int cc = (kc + 1) * 64;
#pragma unroll
            for (int k = 0; k < 2; ++k) {
                pxl[k] = *(const float4*)(xsrc[k] + cc);
                pxh[k] = *(const float4*)(xsrc[k] + cc + 4);
                pwl[k] = *(const float4*)(wsrc[k] + cc);
                pwh[k] = *(const float4*)(wsrc[k] + cc + 4);
            }
        }

        const float2* xsP = smp + (kc & 1) * OUTP_BUF_F2;
        const float2* wsP = xsP + 64*PJS_;
#pragma unroll
        for (int kk = 0; kk < 8; ++kk) {
            uint32_t b0[2], b1[2];
#pragma unroll
            for (int u = 0; u < 2; ++u) {
                float2 bb = wsP[(nw*16 + u*8 + g)*PJS_ + kk*4 + t];
                b0[u] = __float_as_uint(bb.x);
                b1[u] = __float_as_uint(bb.y);
            }
#pragma unroll
            for (int s = 0; s < 2; ++s) {
                int row = mw*32 + s*16 + g;
                float2 a02 = xsP[row*PJS_ + kk*4 + t];
                float2 a13 = xsP[(row+8)*PJS_ + kk*4 + t];
#pragma unroll
                for (int u = 0; u < 2; ++u)
                    mma_tf32(acc[s][u],
                        __float_as_uint(a02.x), __float_as_uint(a13.x),
                        __float_as_uint(a02.y), __float_as_uint(a13.y),
                        b0[u], b1[u]);
            }
        }

        if (kc < 7) {
            float2* buf = smp + ((kc + 1) & 1) * OUTP_BUF_F2;
#pragma unroll
            for (int k = 0; k < 2; ++k) {
                store_tf32_pairs(&buf[xdst[k]], pxl[k], pxh[k]);
                store_tf32_pairs(&buf[wdst[k]], pwl[k], pwh[k]);
            }
            __syncthreads();
        }
    }

#pragma unroll
    for (int u = 0; u < 2; ++u) {
        int col = co0 + nw*16 + u*8 + 2*t;
        float2 bv = *(const float2*)&cb[col];
#pragma unroll
        for (int s = 0; s < 2; ++s) {
            int rg = rt*64 + mw*32 + s*16 + g;
            *(float2*)&out[(size_t)rg*C_ + col] =
                make_float2(acc[s][u][0] + bv.x, acc[s][u][1] + bv.y);
            *(float2*)&out[(size_t)(rg+8)*C_ + col] =
                make_float2(acc[s][u][2] + bv.x, acc[s][u][3] + bv.y);
        }
    }
}

// =====================================================================
extern "C" void kernel_launch(void* const* d_in, const int* in_sizes, int n_in,
                              void* d_out, int out_size)
{
    const float* x0 = (const float*)d_in[0];
    const float* x1 = (const float*)d_in[1];
    const float* x2 = (const float*)d_in[2];
    const float* qw = (const float*)d_in[3];
    const float* qb = (const float*)d_in[4];
    const float* kw = (const float*)d_in[5];
    const float* kb = (const float*)d_in[6];
    const float* vw = (const float*)d_in[7];
    const float* vb = (const float*)d_in[8];
    const float* cw = (const float*)d_in[9];
    const float* cb = (const float*)d_in[10];
    float* out = (float*)d_out;

    cudaFuncSetAttribute(proj_kernel, cudaFuncAttributeMaxDynamicSharedMemorySize,
                         PROJ_SMEM_BYTES);
    proj_kernel<<<dim3(3, H_, 5), 256, PROJ_SMEM_BYTES>>>(
        x0, x1, x2, qw, qb, kw, kb, vw, vb);

    size_t smem = (size_t)SMEM_FLOATS * sizeof(float);
    cudaFuncSetAttribute(attn_kernel, cudaFuncAttributeMaxDynamicSharedMemorySize, (int)smem);
    attn_kernel<<<dim3(T_/ITILE_, BH_), NTHR_, smem>>>();

    cudaFuncSetAttribute(outproj_kernel, cudaFuncAttributeMaxDynamicSharedMemorySize,
                         OUTP_SMEM_BYTES);
    outproj_kernel<<<dim3(6, 8), 256, OUTP_SMEM_BYTES>>>(cw, cb, out);
}

// round 13
// speedup vs baseline: 1.2207x; 1.0147x over previous
#include <cuda_runtime.h>
#include <math_constants.h>
#include <stdint.h>

#define B_ 2
#define T_ 192
#define C_ 512
#define H_ 8
#define HS_ 64
#define ORDER_ 3
#define BH_ (B_*H_)

#define NTHR_ 512

// ---- attn smem float offsets ----
#define OFF_K1B  0                      // [192][40] u32 bf16x2 pair-permuted
#define OFF_K2F  7680                   // [192][40] u32 bf16x2 pair-permuted
#define OFF_V2F  15360                  // [64][104] u32 bf16x2 transposed+permuted
#define OFF_V1S  22016                  // [192][72] fp32 (64 data + pad)
#define OFF_YS   35840                  // [2][16][64]
#define OFF_RED  37888                  // [32]
#define OFF_SCR  37920                  // [192][68] staging scratch
#define SMEM_FLOATS 50976               // 203904 B

// ---- GEMM kernels: pair-permuted tf32 staging, stride 36 float2 ----
#define PJS_ 36
#define PROJ_BUF_F2   (128*PJS_ + 64*PJS_)          // one buffer (float2)
#define PROJ_SMEM_BYTES (2 * PROJ_BUF_F2 * 8)       // 110592 B
#define OUTP_BUF_F2   (64*PJS_ + 64*PJS_)
#define OUTP_SMEM_BYTES (2 * OUTP_BUF_F2 * 8)       // 73728 B

#define QSCALE_ (0.125f * 1.4426950408889634f)

// ---- device scratch ----
__device__ float g_Q [BH_*T_*HS_];
__device__ float g_K1[BH_*T_*HS_];
__device__ float g_K2[BH_*T_*HS_];
__device__ float g_V1[BH_*T_*HS_];
__device__ float g_V2[BH_*T_*HS_];
__device__ float g_Y [B_*T_*C_];

typedef unsigned long long u64;

__device__ __forceinline__ uint32_t bf2(float lo, float hi) {
    uint32_t r;
    asm("cvt.rn.bf16x2.f32 %0, %1, %2;" : "=r"(r) : "f"(hi), "f"(lo));
    return r;
}
__device__ __forceinline__ uint32_t mulbf2(uint32_t a, uint32_t b) {
    uint32_t r;
    asm("mul.bf16x2 %0, %1, %2;" : "=r"(r) : "r"(a), "r"(b));
    return r;
}
__device__ __forceinline__ float ex2f(float x) {
    float r;
    asm("ex2.approx.f32 %0, %1;" : "=f"(r) : "f"(x));
    return r;
}
__device__ __forceinline__ float f2tf(float f) {
    uint32_t r;
    asm("cvt.rna.tf32.f32 %0, %1;" : "=r"(r) : "f"(f));
    return __uint_as_float(r);
}
__device__ __forceinline__ void mma_bf16(float* c,
    uint32_t a0, uint32_t a1, uint32_t a2, uint32_t a3,
    uint32_t b0, uint32_t b1)
{
    asm volatile("mma.sync.aligned.m16n8k16.row.col.f32.bf16.bf16.f32 "
        "{%0,%1,%2,%3}, {%4,%5,%6,%7}, {%8,%9}, {%0,%1,%2,%3};"
        : "+f"(c[0]), "+f"(c[1]), "+f"(c[2]), "+f"(c[3])
        : "r"(a0), "r"(a1), "r"(a2), "r"(a3), "r"(b0), "r"(b1));
}
__device__ __forceinline__ void mma_tf32(float* c,
    uint32_t a0, uint32_t a1, uint32_t a2, uint32_t a3,
    uint32_t b0, uint32_t b1)
{
    asm volatile("mma.sync.aligned.m16n8k8.row.col.f32.tf32.tf32.f32 "
        "{%0,%1,%2,%3}, {%4,%5,%6,%7}, {%8,%9}, {%0,%1,%2,%3};"
        : "+f"(c[0]), "+f"(c[1]), "+f"(c[2]), "+f"(c[3])
        : "r"(a0), "r"(a1), "r"(a2), "r"(a3), "r"(b0), "r"(b1));
}
__device__ __forceinline__ float warpSum(float v) {
#pragma unroll
    for (int o = 16; o; o >>= 1) v += __shfl_xor_sync(0xffffffffu, v, o);
    return v;
}

// convert 8 floats (lo,hi float4 regs) -> 4 pair-permuted tf32 float2 in smem
__device__ __forceinline__ void store_tf32_pairs(float2* d, float4 lo, float4 hi) {
    d[0] = make_float2(f2tf(lo.x), f2tf(hi.x));
    d[1] = make_float2(f2tf(lo.y), f2tf(hi.y));
    d[2] = make_float2(f2tf(lo.z), f2tf(hi.z));
    d[3] = make_float2(f2tf(lo.w), f2tf(hi.w));
}

// =====================================================================
// Kernel 1: per-modality projection as 384x512x512 tf32 GEMM,
// double-buffered, 512 threads (4 warps/SMSP for latency hiding).
// grid (3, 8, 5), block 512.
// =====================================================================
__global__ void __launch_bounds__(512) proj_kernel(
    const float* __restrict__ x0, const float* __restrict__ x1,
    const float* __restrict__ x2,
    const float* __restrict__ qw, const float* __restrict__ qb,
    const float* __restrict__ kw, const float* __restrict__ kb,
    const float* __restrict__ vw, const float* __restrict__ vb)
{
    extern __shared__ float2 smp[];

    int rt = blockIdx.x;               // 128-row tile
    int h  = blockIdx.y;               // head == 64-col tile
    int m  = blockIdx.z;

    const float* x; const float* w; const float* bias; float* out; int o;
    switch (m) {
        case 0:  x = x0; w = qw; bias = qb; out = g_Q;  o = 0; break;
        case 1:  x = x1; w = kw; bias = kb; out = g_K1; o = 1; break;
        case 2:  x = x2; w = kw; bias = kb; out = g_K2; o = 2; break;
        case 3:  x = x1; w = vw; bias = vb; out = g_V1; o = 1; break;
        default: x = x2; w = vw; bias = vb; out = g_V2; o = 2; break;
    }
    const float* wrow = w + (size_t)(h*ORDER_ + o)*HS_*C_;
    const float* brow = bias + (h*ORDER_ + o)*HS_;

    int tid = threadIdx.x;
    int lane = tid & 31, wid = tid >> 5;
    int g = lane >> 2, t = lane & 3;
    int mw = wid & 3;     // 32-row warp tile (4)
    int nw = wid >> 2;    // 16-col warp tile (4)

    // per-thread staging assignments
    const float* xsrc[2];
    int xdst[2];
#pragma unroll
    for (int k = 0; k < 2; ++k) {
        int idx = tid + k*512;
        int r = idx >> 3, sg = idx & 7;
        int rg = rt*128 + r;
        int bb = rg >= T_;
        int tt = rg - bb*T_;
        xsrc[k] = x + ((size_t)bb*T_ + tt)*C_ + sg*8;
        xdst[k] = r*PJS_ + sg*4;
    }
    const float* wsrc;
    int wdst;
    {
        int r = tid >> 3, sg = tid & 7;
        wsrc = wrow + (size_t)r*C_ + sg*8;
        wdst = 128*PJS_ + r*PJS_ + sg*4;
    }

    float4 pxl[2], pxh[2], pwl, pwh;
#pragma unroll
    for (int k = 0; k < 2; ++k) {
        pxl[k] = *(const float4*)(xsrc[k]);
        pxh[k] = *(const float4*)(xsrc[k] + 4);
    }
    pwl = *(const float4*)(wsrc);
    pwh = *(const float4*)(wsrc + 4);
    {
        float2* buf = smp;
#pragma unroll
        for (int k = 0; k < 2; ++k) store_tf32_pairs(&buf[xdst[k]], pxl[k], pxh[k]);
        store_tf32_pairs(&buf[wdst], pwl, pwh);
    }
    __syncthreads();

    float acc[2][2][4] = {};

    for (int kc = 0; kc < 8; ++kc) {
        if (kc < 7) {
            int cc = (kc + 1) * 64;
#pragma unroll
            for (int k = 0; k < 2; ++k) {
                pxl[k] = *(const float4*)(xsrc[k] + cc);
                pxh[k] = *(const float4*)(xsrc[k] + cc + 4);
            }
            pwl = *(const float4*)(wsrc + cc);
            pwh = *(const float4*)(wsrc + cc + 4);
        }

        const float2* xsP = smp + (kc & 1) * PROJ_BUF_F2;
        const float2* wsP = xsP + 128*PJS_;
#pragma unroll
        for (int kk = 0; kk < 8; ++kk) {
            uint32_t b0[2], b1[2];
#pragma unroll
            for (int u = 0; u < 2; ++u) {
                float2 bb = wsP[(nw*16 + u*8 + g)*PJS_ + kk*4 + t];
                b0[u] = __float_as_uint(bb.x);
                b1[u] = __float_as_uint(bb.y);
            }
#pragma unroll
            for (int s = 0; s < 2; ++s) {
                int row = mw*32 + s*16 + g;
                float2 a02 = xsP[row*PJS_ + kk*4 + t];
                float2 a13 = xsP[(row+8)*PJS_ + kk*4 + t];
#pragma unroll
                for (int u = 0; u < 2; ++u)
                    mma_tf32(acc[s][u],
                        __float_as_uint(a02.x), __float_as_uint(a13.x),
                        __float_as_uint(a02.y), __float_as_uint(a13.y),
                        b0[u], b1[u]);
            }
        }

        if (kc < 7) {
            float2* buf = smp + ((kc + 1) & 1) * PROJ_BUF_F2;
#pragma unroll
            for (int k = 0; k < 2; ++k) store_tf32_pairs(&buf[xdst[k]], pxl[k], pxh[k]);
            store_tf32_pairs(&buf[wdst], pwl, pwh);
            __syncthreads();
        }
    }

#pragma unroll
    for (int u = 0; u < 2; ++u) {
        int col = nw*16 + u*8 + 2*t;
        float2 bv = *(const float2*)&brow[col];
#pragma unroll
        for (int s = 0; s < 2; ++s) {
#pragma unroll
            for (int half = 0; half < 2; ++half) {
                int rg = rt*128 + mw*32 + s*16 + g + half*8;
                int bb = rg >= T_;
                int tt = rg - bb*T_;
                *(float2*)&out[(size_t)((bb*H_ + h)*T_ + tt)*HS_ + col] =
                    make_float2(acc[s][u][2*half] + bv.x,
                                acc[s][u][2*half+1] + bv.y);
            }
        }
    }
}

// =====================================================================
// Kernel 2: order-3 attention, flat 148-CTA query chunking
// (56 CTAs x 22 q + 92 x 20 q = 3072). Pairs never straddle bh (even
// starts). K/V re-staged on bh change. bf16 mma, register-resident P.
// Fixed-shift softmax (validated R2-R12).
// =====================================================================
__global__ void __launch_bounds__(NTHR_, 1) attn_kernel()
{
    extern __shared__ float sm[];
    uint32_t* K1b = (uint32_t*)(sm + OFF_K1B);  // [192][40]
    uint32_t* K2f = (uint32_t*)(sm + OFF_K2F);  // [192][40]
    uint32_t* V2f = (uint32_t*)(sm + OFF_V2F);  // [64][104]
    float* V1s = sm + OFF_V1S;                  // [192][72]
    float* Ys  = sm + OFF_YS;                   // [2][16][64]
    float* red = sm + OFF_RED;
    float* scr = sm + OFF_SCR;                  // [192][68]

    int cta = blockIdx.x;
    int start  = (cta < 56) ? 22*cta : 20*cta + 112;
    int npairs = (cta < 56) ? 11 : 10;

    int tid  = threadIdx.x;
    int lane = tid & 31, wid = tid >> 5;
    int g = lane >> 2;
    int t = lane & 3;
    int mt = wid & 3;     // 16 j-rows within strip
    int ng = wid >> 2;    // GEMM1 n-block (48) == GEMM2 k-block (48)

    int staged_bh = -1;

    for (int p = 0; p < npairs; ++p) {
        int gq = start + 2*p;
        int bh = gq / T_;
        int i0 = gq - bh*T_;

        // ---- (re)stage K/V for this bh (uniform branch; prior pair ends
        //      with __syncthreads so old tiles are fully consumed) ----
        if (bh != staged_bh) {
            staged_bh = bh;
            const float* K1g = g_K1 + (size_t)bh*T_*HS_;
            const float* K2g = g_K2 + (size_t)bh*T_*HS_;
            const float* V1g = g_V1 + (size_t)bh*T_*HS_;
            const float* V2g = g_V2 + (size_t)bh*T_*HS_;

            for (int idx = tid; idx < 192*16; idx += NTHR_) {
                int r = idx >> 4, dq = (idx & 15) * 4;
                *(float4*)&scr[r*68 + dq] = ((const float4*)V2g)[idx];
                *(float4*)&V1s[r*72 + dq] = ((const float4*)V1g)[idx];
            }
            for (int task = tid; task < 192*4; task += NTHR_) {
                int r = task >> 2, kk = task & 3;
#pragma unroll
                for (int which = 0; which < 2; ++which) {
                    const float* src = which ? K2g : K1g;
                    uint32_t* dst = (which ? K2f : K1b) + r*40 + kk*8;
                    const float4* s4 = (const float4*)(src + (size_t)r*64 + kk*16);
                    float4 e0 = s4[0], e1 = s4[1], e2 = s4[2], e3 = s4[3];
                    uint32_t p0 = bf2(e0.x, e0.y), p1 = bf2(e0.z, e0.w);
                    uint32_t p2 = bf2(e1.x, e1.y), p3 = bf2(e1.z, e1.w);
                    uint32_t p4 = bf2(e2.x, e2.y), p5 = bf2(e2.z, e2.w);
                    uint32_t p6 = bf2(e3.x, e3.y), p7 = bf2(e3.z, e3.w);
                    *(uint4*)(dst)     = make_uint4(p0, p4, p1, p5);
                    *(uint4*)(dst + 4) = make_uint4(p2, p6, p3, p7);
                }
            }
            __syncthreads();
            for (int task = tid; task < 64*12; task += NTHR_) {
                int kk = task >> 6, d = task & 63;
                float v[16];
#pragma unroll
                for (int i = 0; i < 16; ++i) v[i] = scr[(kk*16 + i)*68 + d];
                uint32_t pk[8];
#pragma unroll
                for (int mm = 0; mm < 8; ++mm) pk[mm] = bf2(v[2*mm], v[2*mm+1]);
                uint32_t* dst = V2f + d*104 + kk*8;
                *(uint4*)(dst)     = make_uint4(pk[0], pk[4], pk[1], pk[5]);
                *(uint4*)(dst + 4) = make_uint4(pk[2], pk[6], pk[3], pk[7]);
            }
            __syncthreads();
        }

        // ---- q fragments via __ldg (L1 broadcast); scale folds log2(e) ----
        uint32_t qp[2][4][2];
        {
            const float* q0 = g_Q + ((size_t)bh*T_ + i0)*HS_;
#pragma unroll
            for (int q = 0; q < 2; ++q) {
                const float* qr = q0 + q*HS_;
#pragma unroll
                for (int kk = 0; kk < 4; ++kk) {
                    float2 qa = __ldg((const float2*)(qr + kk*16 + 2*t));
                    float2 qb = __ldg((const float2*)(qr + kk*16 + 8 + 2*t));
                    qp[q][kk][0] = bf2(qa.x*QSCALE_, qa.y*QSCALE_);
                    qp[q][kk][1] = bf2(qb.x*QSCALE_, qb.y*QSCALE_);
                }
            }
        }
        float l_run[2] = {0.f, 0.f};
        float yl[2][8][2] = {};

        for (int js = 0; js < 3; ++js) {
            int j0 = js * 64;
            int rowA = j0 + mt*16 + g;

            // ---------------- GEMM1: own 16 j-rows x own 48 k-cols ----------
            float c1[2][6][4] = {};
#pragma unroll
            for (int kk = 0; kk < 4; ++kk) {
                uint2 k1lo = *(const uint2*)&K1b[rowA*40 + kk*8 + 2*t];
                uint2 k1hi = *(const uint2*)&K1b[(rowA+8)*40 + kk*8 + 2*t];
                uint32_t A[2][4];
#pragma unroll
                for (int q = 0; q < 2; ++q) {
                    A[q][0] = mulbf2(k1lo.x, qp[q][kk][0]);
                    A[q][1] = mulbf2(k1hi.x, qp[q][kk][0]);
                    A[q][2] = mulbf2(k1lo.y, qp[q][kk][1]);
                    A[q][3] = mulbf2(k1hi.y, qp[q][kk][1]);
                }
#pragma unroll
                for (int s = 0; s < 6; ++s) {
                    int nrow = ng*48 + s*8 + g;
                    uint2 bb = *(const uint2*)&K2f[nrow*40 + kk*8 + 2*t];
                    mma_bf16(c1[0][s], A[0][0], A[0][1], A[0][2], A[0][3], bb.x, bb.y);
                    mma_bf16(c1[1][s], A[1][0], A[1][1], A[1][2], A[1][3], bb.x, bb.y);
                }
            }

            // --------- exp in registers; C-frags ARE the GEMM2 A-frags ------
            uint32_t a[2][3][4];
#pragma unroll
            for (int q = 0; q < 2; ++q) {
#pragma unroll
                for (int m = 0; m < 3; ++m) {
                    float e00 = ex2f(c1[q][2*m][0]),  e01 = ex2f(c1[q][2*m][1]);
                    float e02 = ex2f(c1[q][2*m][2]),  e03 = ex2f(c1[q][2*m][3]);
                    float e10 = ex2f(c1[q][2*m+1][0]), e11 = ex2f(c1[q][2*m+1][1]);
                    float e12 = ex2f(c1[q][2*m+1][2]), e13 = ex2f(c1[q][2*m+1][3]);
                    l_run[q] += ((e00 + e01) + (e02 + e03))
                              + ((e10 + e11) + (e12 + e13));
                    a[q][m][0] = bf2(e00, e01);
                    a[q][m][1] = bf2(e02, e03);
                    a[q][m][2] = bf2(e10, e11);
                    a[q][m][3] = bf2(e12, e13);
                }
            }

            // ------- GEMM2: k-partial (own 48) x all 64 d; no barrier -------
            int jg0 = j0 + mt*16 + g;
#pragma unroll
            for (int u = 0; u < 8; ++u) {
                float w2[2][4] = {};
#pragma unroll
                for (int m = 0; m < 3; ++m) {
                    uint2 bb = *(const uint2*)&V2f[(u*8 + g)*104 + (ng*3 + m)*8 + 2*t];
                    mma_bf16(w2[0], a[0][m][0], a[0][m][1], a[0][m][2], a[0][m][3], bb.x, bb.y);
                    mma_bf16(w2[1], a[1][m][0], a[1][m][1], a[1][m][2], a[1][m][3], bb.x, bb.y);
                }
                int dc = u*8 + 2*t;
                float2 va = *(const float2*)&V1s[jg0*72 + dc];
                float2 vb = *(const float2*)&V1s[(jg0+8)*72 + dc];
#pragma unroll
                for (int q = 0; q < 2; ++q) {
                    yl[q][u][0] += w2[q][0]*va.x + w2[q][2]*vb.x;
                    yl[q][u][1] += w2[q][1]*va.y + w2[q][3]*vb.y;
                }
            }
        }

        // ---- per-query reductions (sum over g via shfl, then 16 warps) ----
#pragma unroll
        for (int q = 0; q < 2; ++q) {
#pragma unroll
            for (int u = 0; u < 8; ++u)
#pragma unroll
                for (int c = 0; c < 2; ++c) {
                    yl[q][u][c] += __shfl_xor_sync(0xffffffffu, yl[q][u][c], 4);
                    yl[q][u][c] += __shfl_xor_sync(0xffffffffu, yl[q][u][c], 8);
                    yl[q][u][c] += __shfl_xor_sync(0xffffffffu, yl[q][u][c], 16);
                }
            float lw = warpSum(l_run[q]);
            if (lane == 0) red[q*16 + wid] = lw;
            if (lane < 4) {
#pragma unroll
                for (int u = 0; u < 8; ++u) {
                    Ys[q*1024 + wid*64 + u*8 + 2*lane + 0] = yl[q][u][0];
                    Ys[q*1024 + wid*64 + u*8 + 2*lane + 1] = yl[q][u][1];
                }
            }
        }
        __syncthreads();
        if (tid < 128) {
            int q = tid >> 6, c64 = tid & 63;
            float lt = 0.f;
#pragma unroll
            for (int w = 0; w < 16; ++w) lt += red[q*16 + w];
            float y = 0.f;
#pragma unroll
            for (int w = 0; w < 16; ++w) y += Ys[q*1024 + w*64 + c64];
            int b = bh >> 3, h = bh & 7;
            g_Y[((size_t)(b*T_ + i0 + q)*H_ + h)*HS_ + c64] = y / lt;
        }
        __syncthreads();
    }
}

// =====================================================================
// Kernel 3: output projection as 384x512x512 tf32 GEMM, double-buffered.
// grid (6, 8): 64-row tile x 64-col tile. block 256.
// =====================================================================
__global__ void __launch_bounds__(256) outproj_kernel(
    const float* __restrict__ cw, const float* __restrict__ cb,
    float* __restrict__ out)
{
    extern __shared__ float2 smp[];

    int rt  = blockIdx.x;              // 64-row tile
    int ct  = blockIdx.y;              // 64-col tile
    int co0 = ct * 64;

    int tid = threadIdx.x;
    int lane = tid & 31, wid = tid >> 5;
    int g = lane >> 2, t = lane & 3;
    int mw = wid & 1;     // 32-row warp tile
    int nw = wid >> 1;    // 16-col warp tile

    const float* xsrc[2];
    int xdst[2];
    const float* wsrc[2];
    int wdst[2];
#pragma unroll
    for (int k = 0; k < 2; ++k) {
        int idx = tid + k*256;
        int r = idx >> 3, sg = idx & 7;
        xsrc[k] = g_Y + (size_t)(rt*64 + r)*C_ + sg*8;
        xdst[k] = r*PJS_ + sg*4;
        wsrc[k] = cw + (size_t)(co0 + r)*C_ + sg*8;
        wdst[k] = 64*PJS_ + r*PJS_ + sg*4;
    }

    float4 pxl[2], pxh[2], pwl[2], pwh[2];
#pragma unroll
    for (int k = 0; k < 2; ++k) {
        pxl[k] = *(const float4*)(xsrc[k]);
        pxh[k] = *(const float4*)(xsrc[k] + 4);
        pwl[k] = *(const float4*)(wsrc[k]);
        pwh[k] = *(const float4*)(wsrc[k] + 4);
    }
    {
        float2* buf = smp;
#pragma unroll
        for (int k = 0; k < 2; ++k) {
            store_tf32_pairs(&buf[xdst[k]], pxl[k], pxh[k]);
            store_tf32_pairs(&buf[wdst[k]], pwl[k], pwh[k]);
        }
    }
    __syncthreads();

    float acc[2][2][4] = {};

    for (int kc = 0; kc < 8; ++kc) {
        if (kc < 7) {
            int cc = (kc + 1) * 64;
#pragma unroll
            for (int k = 0; k < 2; ++k) {
                pxl[k] = *(const float4*)(xsrc[k] + cc);
                pxh[k] = *(const float4*)(xsrc[k] + cc + 4);
                pwl[k] = *(const float4*)(wsrc[k] + cc);
                pwh[k] = *(const float4*)(wsrc[k] + cc + 4);
            }
        }

        const float2* xsP = smp + (kc & 1) * OUTP_BUF_F2;
        const float2* wsP = xsP + 64*PJS_;
#pragma unroll
        for (int kk = 0; kk < 8; ++kk) {
            uint32_t b0[2], b1[2];
#pragma unroll
            for (int u = 0; u < 2; ++u) {
                float2 bb = wsP[(nw*16 + u*8 + g)*PJS_ + kk*4 + t];
                b0[u] = __float_as_uint(bb.x);
                b1[u] = __float_as_uint(bb.y);
            }
#pragma unroll
            for (int s = 0; s < 2; ++s) {
                int row = mw*32 + s*16 + g;
                float2 a02 = xsP[row*PJS_ + kk*4 + t];
                float2 a13 = xsP[(row+8)*PJS_ + kk*4 + t];
#pragma unroll
                for (int u = 0; u < 2; ++u)
                    mma_tf32(acc[s][u],
                        __float_as_uint(a02.x), __float_as_uint(a13.x),
                        __float_as_uint(a02.y), __float_as_uint(a13.y),
                        b0[u], b1[u]);
            }
        }

        if (kc < 7) {
            float2* buf = smp + ((kc + 1) & 1) * OUTP_BUF_F2;
#pragma unroll
            for (int k = 0; k < 2; ++k) {
                store_tf32_pairs(&buf[xdst[k]], pxl[k], pxh[k]);
                store_tf32_pairs(&buf[wdst[k]], pwl[k], pwh[k]);
            }
            __syncthreads();
        }
    }

#pragma unroll
    for (int u = 0; u < 2; ++u) {
        int col = co0 + nw*16 + u*8 + 2*t;
        float2 bv = *(const float2*)&cb[col];
#pragma unroll
        for (int s = 0; s < 2; ++s) {
            int rg = rt*64 + mw*32 + s*16 + g;
            *(float2*)&out[(size_t)rg*C_ + col] =
                make_float2(acc[s][u][0] + bv.x, acc[s][u][1] + bv.y);
            *(float2*)&out[(size_t)(rg+8)*C_ + col] =
                make_float2(acc[s][u][2] + bv.x, acc[s][u][3] + bv.y);
        }
    }
}

// =====================================================================
extern "C" void kernel_launch(void* const* d_in, const int* in_sizes, int n_in,
                              void* d_out, int out_size)
{
    const float* x0 = (const float*)d_in[0];
    const float* x1 = (const float*)d_in[1];
    const float* x2 = (const float*)d_in[2];
    const float* qw = (const float*)d_in[3];
    const float* qb = (const float*)d_in[4];
    const float* kw = (const float*)d_in[5];
    const float* kb = (const float*)d_in[6];
    const float* vw = (const float*)d_in[7];
    const float* vb = (const float*)d_in[8];
    const float* cw = (const float*)d_in[9];
    const float* cb = (const float*)d_in[10];
    float* out = (float*)d_out;

    cudaFuncSetAttribute(proj_kernel, cudaFuncAttributeMaxDynamicSharedMemorySize,
                         PROJ_SMEM_BYTES);
    proj_kernel<<<dim3(3, H_, 5), 512, PROJ_SMEM_BYTES>>>(
        x0, x1, x2, qw, qb, kw, kb, vw, vb);

    size_t smem = (size_t)SMEM_FLOATS * sizeof(float);
    cudaFuncSetAttribute(attn_kernel, cudaFuncAttributeMaxDynamicSharedMemorySize, (int)smem);
    attn_kernel<<<148, NTHR_, smem>>>();

    cudaFuncSetAttribute(outproj_kernel, cudaFuncAttributeMaxDynamicSharedMemorySize,
                         OUTP_SMEM_BYTES);
    outproj_kernel<<<dim3(6, 8), 256, OUTP_SMEM_BYTES>>>(cw, cb, out);
}

// round 15
// speedup vs baseline: 1.2210x; 1.0002x over previous
#include <cuda_runtime.h>
#include <math_constants.h>
#include <stdint.h>

#define B_ 2
#define T_ 192
#define C_ 512
#define H_ 8
#define HS_ 64
#define ORDER_ 3
#define BH_ (B_*H_)

#define NTHR_ 512

// ---- attn smem float offsets ----
#define OFF_K1B  0                      // [192][40] u32 bf16x2 pair-permuted
#define OFF_K2F  7680                   // [192][40] u32 bf16x2 pair-permuted
#define OFF_V2F  15360                  // [64][104] u32 bf16x2 transposed+permuted
#define OFF_V1S  22016                  // [192][72] fp32 (64 data + pad)
#define OFF_YS   35840                  // [2][16][64]
#define OFF_RED  37888                  // [32]
#define OFF_SCR  37920                  // [192][68] staging scratch
#define SMEM_FLOATS 50976               // 203904 B

// ---- GEMM kernels: pair-permuted tf32 staging, stride 36 float2 ----
#define PJS_ 36
#define PROJ_BUF_F2   (128*PJS_ + 64*PJS_)          // one buffer (float2)
#define PROJ_SMEM_BYTES (3 * PROJ_BUF_F2 * 8)       // 165888 B (triple buffer)
#define OUTP_BUF_F2   (64*PJS_ + 64*PJS_)
#define OUTP_SMEM_BYTES (3 * OUTP_BUF_F2 * 8)       // 110592 B

#define QSCALE_ (0.125f * 1.4426950408889634f)

// ---- device scratch ----
__device__ float g_Q [BH_*T_*HS_];
__device__ float g_K1[BH_*T_*HS_];
__device__ float g_K2[BH_*T_*HS_];
__device__ float g_V1[BH_*T_*HS_];
__device__ float g_V2[BH_*T_*HS_];
__device__ float g_Y [B_*T_*C_];

typedef unsigned long long u64;

__device__ __forceinline__ uint32_t bf2(float lo, float hi) {
    uint32_t r;
    asm("cvt.rn.bf16x2.f32 %0, %1, %2;" : "=r"(r) : "f"(hi), "f"(lo));
    return r;
}
__device__ __forceinline__ uint32_t mulbf2(uint32_t a, uint32_t b) {
    uint32_t r;
    asm("mul.bf16x2 %0, %1, %2;" : "=r"(r) : "r"(a), "r"(b));
    return r;
}
__device__ __forceinline__ float ex2f(float x) {
    float r;
    asm("ex2.approx.f32 %0, %1;" : "=f"(r) : "f"(x));
    return r;
}
__device__ __forceinline__ float f2tf(float f) {
    uint32_t r;
    asm("cvt.rna.tf32.f32 %0, %1;" : "=r"(r) : "f"(f));
    return __uint_as_float(r);
}
__device__ __forceinline__ void mma_bf16(float* c,
    uint32_t a0, uint32_t a1, uint32_t a2, uint32_t a3,
    uint32_t b0, uint32_t b1)
{
    asm volatile("mma.sync.aligned.m16n8k16.row.col.f32.bf16.bf16.f32 "
        "{%0,%1,%2,%3}, {%4,%5,%6,%7}, {%8,%9}, {%0,%1,%2,%3};"
        : "+f"(c[0]), "+f"(c[1]), "+f"(c[2]), "+f"(c[3])
        : "r"(a0), "r"(a1), "r"(a2), "r"(a3), "r"(b0), "r"(b1));
}
__device__ __forceinline__ void mma_tf32(float* c,
    uint32_t a0, uint32_t a1, uint32_t a2, uint32_t a3,
    uint32_t b0, uint32_t b1)
{
    asm volatile("mma.sync.aligned.m16n8k8.row.col.f32.tf32.tf32.f32 "
        "{%0,%1,%2,%3}, {%4,%5,%6,%7}, {%8,%9}, {%0,%1,%2,%3};"
        : "+f"(c[0]), "+f"(c[1]), "+f"(c[2]), "+f"(c[3])
        : "r"(a0), "r"(a1), "r"(a2), "r"(a3), "r"(b0), "r"(b1));
}
__device__ __forceinline__ float warpSum(float v) {
#pragma unroll
    for (int o = 16; o; o >>= 1) v += __shfl_xor_sync(0xffffffffu, v, o);
    return v;
}

// convert 8 floats (lo,hi float4 regs) -> 4 pair-permuted tf32 float2 in smem
__device__ __forceinline__ void store_tf32_pairs(float2* d, float4 lo, float4 hi) {
    d[0] = make_float2(f2tf(lo.x), f2tf(hi.x));
    d[1] = make_float2(f2tf(lo.y), f2tf(hi.y));
    d[2] = make_float2(f2tf(lo.z), f2tf(hi.z));
    d[3] = make_float2(f2tf(lo.w), f2tf(hi.w));
}

// =====================================================================
// Kernel 1: per-modality projection as 384x512x512 tf32 GEMM,
// TRIPLE-buffered (prefetch distance 2), 512 threads.
// Buffer rotation: chunk c lives in buffer c%3. At iteration kc we write
// chunk kc+2 into buffer (kc+2)%3 == (kc-1)%3, whose tenant (chunk kc-1)
// was fully consumed before the barrier ending iteration kc-1.
// grid (3, 8, 5), block 512.
// =====================================================================
__global__ void __launch_bounds__(512) proj_kernel(
    const float* __restrict__ x0, const float* __restrict__ x1,
    const float* __restrict__ x2,
    const float* __restrict__ qw, const float* __restrict__ qb,
    const float* __restrict__ kw, const float* __restrict__ kb,
    const float* __restrict__ vw, const float* __restrict__ vb)
{
    extern __shared__ float2 smp[];

    int rt = blockIdx.x;               // 128-row tile
    int h  = blockIdx.y;               // head == 64-col tile
    int m  = blockIdx.z;

    const float* x; const float* w; const float* bias; float* out; int o;
    switch (m) {
        case 0:  x = x0; w = qw; bias = qb; out = g_Q;  o = 0; break;
        case 1:  x = x1; w = kw; bias = kb; out = g_K1; o = 1; break;
        case 2:  x = x2; w = kw; bias = kb; out = g_K2; o = 2; break;
        case 3:  x = x1; w = vw; bias = vb; out = g_V1; o = 1; break;
        default: x = x2; w = vw; bias = vb; out = g_V2; o = 2; break;
    }
    const float* wrow = w + (size_t)(h*ORDER_ + o)*HS_*C_;
    const float* brow = bias + (h*ORDER_ + o)*HS_;

    int tid = threadIdx.x;
    int lane = tid & 31, wid = tid >> 5;
    int g = lane >> 2, t = lane & 3;
    int mw = wid & 3;     // 32-row warp tile (4)
    int nw = wid >> 2;    // 16-col warp tile (4)

    // per-thread staging assignments
    const float* xsrc[2];
    int xdst[2];
#pragma unroll
    for (int k = 0; k < 2; ++k) {
        int idx = tid + k*512;
        int r = idx >> 3, sg = idx & 7;
        int rg = rt*128 + r;
        int bb = rg >= T_;
        int tt = rg - bb*T_;
        xsrc[k] = x + ((size_t)bb*T_ + tt)*C_ + sg*8;
        xdst[k] = r*PJS_ + sg*4;
    }
    const float* wsrc;
    int wdst;
    {
        int r = tid >> 3, sg = tid & 7;
        wsrc = wrow + (size_t)r*C_ + sg*8;
        wdst = 128*PJS_ + r*PJS_ + sg*4;
    }

    float4 pxl[2], pxh[2], pwl, pwh;
    // prologue: stage chunks 0 and 1 into buffers 0, 1
#pragma unroll
    for (int c = 0; c < 2; ++c) {
        int cc = c * 64;
#pragma unroll
        for (int k = 0; k < 2; ++k) {
            pxl[k] = *(const float4*)(xsrc[k] + cc);
            pxh[k] = *(const float4*)(xsrc[k] + cc + 4);
        }
        pwl = *(const float4*)(wsrc + cc);
        pwh = *(const float4*)(wsrc + cc + 4);
        float2* buf = smp + c * PROJ_BUF_F2;
#pragma unroll
        for (int k = 0; k < 2; ++k) store_tf32_pairs(&buf[xdst[k]], pxl[k], pxh[k]);
        store_tf32_pairs(&buf[wdst], pwl, pwh);
    }
    __syncthreads();

    float acc[2][2][4] = {};
    int bufidx = 0;    // = kc % 3
    int wrbuf  = 2;    // = (kc+2) % 3

    for (int kc = 0; kc < 8; ++kc) {
        // prefetch chunk kc+2 (consumed 2 iterations from now)
        if (kc + 2 < 8) {
            int cc = (kc + 2) * 64;
#pragma unroll
            for (int k = 0; k < 2; ++k) {
                pxl[k] = *(const float4*)(xsrc[k] + cc);
                pxh[k] = *(const float4*)(xsrc[k] + cc + 4);
            }
            pwl = *(const float4*)(wsrc + cc);
            pwh = *(const float4*)(wsrc + cc + 4);
        }

        const float2* xsP = smp + bufidx * PROJ_BUF_F2;
        const float2* wsP = xsP + 128*PJS_;
#pragma unroll
        for (int kk = 0; kk < 8; ++kk) {
            uint32_t b0[2], b1[2];
#pragma unroll
            for (int u = 0; u < 2; ++u) {
                float2 bb = wsP[(nw*16 + u*8 + g)*PJS_ + kk*4 + t];
                b0[u] = __float_as_uint(bb.x);
                b1[u] = __float_as_uint(bb.y);
            }
#pragma unroll
            for (int s = 0; s < 2; ++s) {
                int row = mw*32 + s*16 + g;
                float2 a02 = xsP[row*PJS_ + kk*4 + t];
                float2 a13 = xsP[(row+8)*PJS_ + kk*4 + t];
#pragma unroll
                for (int u = 0; u < 2; ++u)
                    mma_tf32(acc[s][u],
                        __float_as_uint(a02.x), __float_as_uint(a13.x),
                        __float_as_uint(a02.y), __float_as_uint(a13.y),
                        b0[u], b1[u]);
            }
        }
        __syncthreads();   // chunk kc consumed by all warps

        if (kc + 2 < 8) {
            float2* buf = smp + wrbuf * PROJ_BUF_F2;   // buffer (kc+2)%3
#pragma unroll
            for (int k = 0; k < 2; ++k) store_tf32_pairs(&buf[xdst[k]], pxl[k], pxh[k]);
            store_tf32_pairs(&buf[wdst], pwl, pwh);
        }
        bufidx = (bufidx + 1 == 3) ? 0 : bufidx + 1;
        wrbuf  = (wrbuf  + 1 == 3) ? 0 : wrbuf  + 1;
    }

#pragma unroll
    for (int u = 0; u < 2; ++u) {
        int col = nw*16 + u*8 + 2*t;
        float2 bv = *(const float2*)&brow[col];
#pragma unroll
        for (int s = 0; s < 2; ++s) {
#pragma unroll
            for (int half = 0; half < 2; ++half) {
                int rg = rt*128 + mw*32 + s*16 + g + half*8;
                int bb = rg >= T_;
                int tt = rg - bb*T_;
                *(float2*)&out[(size_t)((bb*H_ + h)*T_ + tt)*HS_ + col] =
                    make_float2(acc[s][u][2*half] + bv.x,
                                acc[s][u][2*half+1] + bv.y);
            }
        }
    }
}

// =====================================================================
// Kernel 2: order-3 attention (R13-identical), flat 148-CTA chunking,
// bf16 mma, register-resident P. Fixed-shift softmax (validated R2-R13).
// =====================================================================
__global__ void __launch_bounds__(NTHR_, 1) attn_kernel()
{
    extern __shared__ float sm[];
    uint32_t* K1b = (uint32_t*)(sm + OFF_K1B);  // [192][40]
    uint32_t* K2f = (uint32_t*)(sm + OFF_K2F);  // [192][40]
    uint32_t* V2f = (uint32_t*)(sm + OFF_V2F);  // [64][104]
    float* V1s = sm + OFF_V1S;                  // [192][72]
    float* Ys  = sm + OFF_YS;                   // [2][16][64]
    float* red = sm + OFF_RED;
    float* scr = sm + OFF_SCR;                  // [192][68]

    int cta = blockIdx.x;
    int start  = (cta < 56) ? 22*cta : 20*cta + 112;
    int npairs = (cta < 56) ? 11 : 10;

    int tid  = threadIdx.x;
    int lane = tid & 31, wid = tid >> 5;
    int g = lane >> 2;
    int t = lane & 3;
    int mt = wid & 3;     // 16 j-rows within strip
    int ng = wid >> 2;    // GEMM1 n-block (48) == GEMM2 k-block (48)

    int staged_bh = -1;

    for (int p = 0; p < npairs; ++p) {
        int gq = start + 2*p;
        int bh = gq / T_;
        int i0 = gq - bh*T_;

        if (bh != staged_bh) {
            staged_bh = bh;
            const float* K1g = g_K1 + (size_t)bh*T_*HS_;
            const float* K2g = g_K2 + (size_t)bh*T_*HS_;
            const float* V1g = g_V1 + (size_t)bh*T_*HS_;
            const float* V2g = g_V2 + (size_t)bh*T_*HS_;

            for (int idx = tid; idx < 192*16; idx += NTHR_) {
                int r = idx >> 4, dq = (idx & 15) * 4;
                *(float4*)&scr[r*68 + dq] = ((const float4*)V2g)[idx];
                *(float4*)&V1s[r*72 + dq] = ((const float4*)V1g)[idx];
            }
            for (int task = tid; task < 192*4; task += NTHR_) {
                int r = task >> 2, kk = task & 3;
#pragma unroll
                for (int which = 0; which < 2; ++which) {
                    const float* src = which ? K2g : K1g;
                    uint32_t* dst = (which ? K2f : K1b) + r*40 + kk*8;
                    const float4* s4 = (const float4*)(src + (size_t)r*64 + kk*16);
                    float4 e0 = s4[0], e1 = s4[1], e2 = s4[2], e3 = s4[3];
                    uint32_t p0 = bf2(e0.x, e0.y), p1 = bf2(e0.z, e0.w);
                    uint32_t p2 = bf2(e1.x, e1.y), p3 = bf2(e1.z, e1.w);
                    uint32_t p4 = bf2(e2.x, e2.y), p5 = bf2(e2.z, e2.w);
                    uint32_t p6 = bf2(e3.x, e3.y), p7 = bf2(e3.z, e3.w);
                    *(uint4*)(dst)     = make_uint4(p0, p4, p1, p5);
                    *(uint4*)(dst + 4) = make_uint4(p2, p6, p3, p7);
                }
            }
            __syncthreads();
            for (int task = tid; task < 64*12; task += NTHR_) {
                int kk = task >> 6, d = task & 63;
                float v[16];
#pragma unroll
                for (int i = 0; i < 16; ++i) v[i] = scr[(kk*16 + i)*68 + d];
                uint32_t pk[8];
#pragma unroll
                for (int mm = 0; mm < 8; ++mm) pk[mm] = bf2(v[2*mm], v[2*mm+1]);
                uint32_t* dst = V2f + d*104 + kk*8;
                *(uint4*)(dst)     = make_uint4(pk[0], pk[4], pk[1], pk[5]);
                *(uint4*)(dst + 4) = make_uint4(pk[2], pk[6], pk[3], pk[7]);
            }
            __syncthreads();
        }

        // ---- q fragments via __ldg (L1 broadcast); scale folds log2(e) ----
        uint32_t qp[2][4][2];
        {
            const float* q0 = g_Q + ((size_t)bh*T_ + i0)*HS_;
#pragma unroll
            for (int q = 0; q < 2; ++q) {
                const float* qr = q0 + q*HS_;
#pragma unroll
                for (int kk = 0; kk < 4; ++kk) {
                    float2 qa = __ldg((const float2*)(qr + kk*16 + 2*t));
                    float2 qb = __ldg((const float2*)(qr + kk*16 + 8 + 2*t));
                    qp[q][kk][0] = bf2(qa.x*QSCALE_, qa.y*QSCALE_);
                    qp[q][kk][1] = bf2(qb.x*QSCALE_, qb.y*QSCALE_);
                }
            }
        }
        float l_run[2] = {0.f, 0.f};
        float yl[2][8][2] = {};

        for (int js = 0; js < 3; ++js) {
            int j0 = js * 64;
            int rowA = j0 + mt*16 + g;

            // ---------------- GEMM1: own 16 j-rows x own 48 k-cols ----------
            float c1[2][6][4] = {};
#pragma unroll
            for (int kk = 0; kk < 4; ++kk) {
                uint2 k1lo = *(const uint2*)&K1b[rowA*40 + kk*8 + 2*t];
                uint2 k1hi = *(const uint2*)&K1b[(rowA+8)*40 + kk*8 + 2*t];
                uint32_t A[2][4];
#pragma unroll
                for (int q = 0; q < 2; ++q) {
                    A[q][0] = mulbf2(k1lo.x, qp[q][kk][0]);
                    A[q][1] = mulbf2(k1hi.x, qp[q][kk][0]);
                    A[q][2] = mulbf2(k1lo.y, qp[q][kk][1]);
                    A[q][3] = mulbf2(k1hi.y, qp[q][kk][1]);
                }
#pragma unroll
                for (int s = 0; s < 6; ++s) {
                    int nrow = ng*48 + s*8 + g;
                    uint2 bb = *(const uint2*)&K2f[nrow*40 + kk*8 + 2*t];
                    mma_bf16(c1[0][s], A[0][0], A[0][1], A[0][2], A[0][3], bb.x, bb.y);
                    mma_bf16(c1[1][s], A[1][0], A[1][1], A[1][2], A[1][3], bb.x, bb.y);
                }
            }

            // --------- exp in registers; C-frags ARE the GEMM2 A-frags ------
            uint32_t a[2][3][4];
#pragma unroll
            for (int q = 0; q < 2; ++q) {
#pragma unroll
                for (int m = 0; m < 3; ++m) {
                    float e00 = ex2f(c1[q][2*m][0]),  e01 = ex2f(c1[q][2*m][1]);
                    float e02 = ex2f(c1[q][2*m][2]),  e03 = ex2f(c1[q][2*m][3]);
                    float e10 = ex2f(c1[q][2*m+1][0]), e11 = ex2f(c1[q][2*m+1][1]);
                    float e12 = ex2f(c1[q][2*m+1][2]), e13 = ex2f(c1[q][2*m+1][3]);
                    l_run[q] += ((e00 + e01) + (e02 + e03))
                              + ((e10 + e11) + (e12 + e13));
                    a[q][m][0] = bf2(e00, e01);
                    a[q][m][1] = bf2(e02, e03);
                    a[q][m][2] = bf2(e10, e11);
                    a[q][m][3] = bf2(e12, e13);
                }
            }

            // ------- GEMM2: k-partial (own 48) x all 64 d; no barrier -------
            int jg0 = j0 + mt*16 + g;
#pragma unroll
            for (int u = 0; u < 8; ++u) {
                float w2[2][4] = {};
#pragma unroll
                for (int m = 0; m < 3; ++m) {
                    uint2 bb = *(const uint2*)&V2f[(u*8 + g)*104 + (ng*3 + m)*8 + 2*t];
                    mma_bf16(w2[0], a[0][m][0], a[0][m][1], a[0][m][2], a[0][m][3], bb.x, bb.y);
                    mma_bf16(w2[1], a[1][m][0], a[1][m][1], a[1][m][2], a[1][m][3], bb.x, bb.y);
                }
                int dc = u*8 + 2*t;
                float2 va = *(const float2*)&V1s[jg0*72 + dc];
                float2 vb = *(const float2*)&V1s[(jg0+8)*72 + dc];
#pragma unroll
                for (int q = 0; q < 2; ++q) {
                    yl[q][u][0] += w2[q][0]*va.x + w2[q][2]*vb.x;
                    yl[q][u][1] += w2[q][1]*va.y + w2[q][3]*vb.y;
                }
            }
        }

        // ---- per-query reductions (sum over g via shfl, then 16 warps) ----
#pragma unroll
        for (int q = 0; q < 2; ++q) {
#pragma unroll
            for (int u = 0; u < 8; ++u)
#pragma unroll
                for (int c = 0; c < 2; ++c) {
                    yl[q][u][c] += __shfl_xor_sync(0xffffffffu, yl[q][u][c], 4);
                    yl[q][u][c] += __shfl_xor_sync(0xffffffffu, yl[q][u][c], 8);
                    yl[q][u][c] += __shfl_xor_sync(0xffffffffu, yl[q][u][c], 16);
                }
            float lw = warpSum(l_run[q]);
            if (lane == 0) red[q*16 + wid] = lw;
            if (lane < 4) {
#pragma unroll
                for (int u = 0; u < 8; ++u) {
                    Ys[q*1024 + wid*64 + u*8 + 2*lane + 0] = yl[q][u][0];
                    Ys[q*1024 + wid*64 + u*8 + 2*lane + 1] = yl[q][u][1];
                }
            }
        }
        __syncthreads();
        if (tid < 128) {
            int q = tid >> 6, c64 = tid & 63;
            float lt = 0.f;
#pragma unroll
            for (int w = 0; w < 16; ++w) lt += red[q*16 + w];
            float y = 0.f;
#pragma unroll
            for (int w = 0; w < 16; ++w) y += Ys[q*1024 + w*64 + c64];
            int b = bh >> 3, h = bh & 7;
            g_Y[((size_t)(b*T_ + i0 + q)*H_ + h)*HS_ + c64] = y / lt;
        }
        __syncthreads();
    }
}

// =====================================================================
// Kernel 3: output projection as 384x512x512 tf32 GEMM, TRIPLE-buffered
// (same corrected rotation). grid (6, 8). block 256.
// =====================================================================
__global__ void __launch_bounds__(256) outproj_kernel(
    const float* __restrict__ cw, const float* __restrict__ cb,
    float* __restrict__ out)
{
    extern __shared__ float2 smp[];

    int rt  = blockIdx.x;              // 64-row tile
    int ct  = blockIdx.y;              // 64-col tile
    int co0 = ct * 64;

    int tid = threadIdx.x;
    int lane = tid & 31, wid = tid >> 5;
    int g = lane >> 2, t = lane & 3;
    int mw = wid & 1;     // 32-row warp tile
    int nw = wid >> 1;    // 16-col warp tile

    const float* xsrc[2];
    int xdst[2];
    const float* wsrc[2];
    int wdst[2];
#pragma unroll
    for (int k = 0; k < 2; ++k) {
        int idx = tid + k*256;
        int r = idx >> 3, sg = idx & 7;
        xsrc[k] = g_Y + (size_t)(rt*64 + r)*C_ + sg*8;
        xdst[k] = r*PJS_ + sg*4;
        wsrc[k] = cw + (size_t)(co0 + r)*C_ + sg*8;
        wdst[k] = 64*PJS_ + r*PJS_ + sg*4;
    }

    float4 pxl[2], pxh[2], pwl[2], pwh[2];
    // prologue: stage chunks 0 and 1
#pragma unroll
    for (int c = 0; c < 2; ++c) {
        int cc = c * 64;
#pragma unroll
        for (int k = 0; k < 2; ++k) {
            pxl[k] = *(const float4*)(xsrc[k] + cc);
            pxh[k] = *(const float4*)(xsrc[k] + cc + 4);
            pwl[k] = *(const float4*)(wsrc[k] + cc);
            pwh[k] = *(const float4*)(wsrc[k] + cc + 4);
        }
        float2* buf = smp + c * OUTP_BUF_F2;
#pragma unroll
        for (int k = 0; k < 2; ++k) {
            store_tf32_pairs(&buf[xdst[k]], pxl[k], pxh[k]);
            store_tf32_pairs(&buf[wdst[k]], pwl[k], pwh[k]);
        }
    }
    __syncthreads();

    float acc[2][2][4] = {};
    int bufidx = 0;    // = kc % 3
    int wrbuf  = 2;    // = (kc+2) % 3

    for (int kc = 0; kc < 8; ++kc) {
        if (kc + 2 < 8) {
            int cc = (kc + 2) * 64;
#pragma unroll
            for (int k = 0; k < 2; ++k) {
                pxl[k] = *(const float4*)(xsrc[k] + cc);
                pxh[k] = *(const float4*)(xsrc[k] + cc + 4);
                pwl[k] = *(const float4*)(wsrc[k] + cc);
                pwh[k] = *(const float4*)(wsrc[k] + cc + 4);
            }
        }

        const float2* xsP = smp + bufidx * OUTP_BUF_F2;
        const float2* wsP = xsP + 64*PJS_;
#pragma unroll
        for (int kk = 0; kk < 8; ++kk) {
            uint32_t b0[2], b1[2];
#pragma unroll
            for (int u = 0; u < 2; ++u) {
                float2 bb = wsP[(nw*16 + u*8 + g)*PJS_ + kk*4 + t];
                b0[u] = __float_as_uint(bb.x);
                b1[u] = __float_as_uint(bb.y);
            }
#pragma unroll
            for (int s = 0; s < 2; ++s) {
                int row = mw*32 + s*16 + g;
                float2 a02 = xsP[row*PJS_ + kk*4 + t];
                float2 a13 = xsP[(row+8)*PJS_ + kk*4 + t];
#pragma unroll
                for (int u = 0; u < 2; ++u)
                    mma_tf32(acc[s][u],
                        __float_as_uint(a02.x), __float_as_uint(a13.x),
                        __float_as_uint(a02.y), __float_as_uint(a13.y),
                        b0[u], b1[u]);
            }
        }
        __syncthreads();

        if (kc + 2 < 8) {
            float2* buf = smp + wrbuf * OUTP_BUF_F2;   // buffer (kc+2)%3
#pragma unroll
            for (int k = 0; k < 2; ++k) {
                store_tf32_pairs(&buf[xdst[k]], pxl[k], pxh[k]);
                store_tf32_pairs(&buf[wdst[k]], pwl[k], pwh[k]);
            }
        }
        bufidx = (bufidx + 1 == 3) ? 0 : bufidx + 1;
        wrbuf  = (wrbuf  + 1 == 3) ? 0 : wrbuf  + 1;
    }

#pragma unroll
    for (int u = 0; u < 2; ++u) {
        int col = co0 + nw*16 + u*8 + 2*t;
        float2 bv = *(const float2*)&cb[col];
#pragma unroll
        for (int s = 0; s < 2; ++s) {
            int rg = rt*64 + mw*32 + s*16 + g;
            *(float2*)&out[(size_t)rg*C_ + col] =
                make_float2(acc[s][u][0] + bv.x, acc[s][u][1] + bv.y);
            *(float2*)&out[(size_t)(rg+8)*C_ + col] =
                make_float2(acc[s][u][2] + bv.x, acc[s][u][3] + bv.y);
        }
    }
}

// =====================================================================
extern "C" void kernel_launch(void* const* d_in, const int* in_sizes, int n_in,
                              void* d_out, int out_size)
{
    const float* x0 = (const float*)d_in[0];
    const float* x1 = (const float*)d_in[1];
    const float* x2 = (const float*)d_in[2];
    const float* qw = (const float*)d_in[3];
    const float* qb = (const float*)d_in[4];
    const float* kw = (const float*)d_in[5];
    const float* kb = (const float*)d_in[6];
    const float* vw = (const float*)d_in[7];
    const float* vb = (const float*)d_in[8];
    const float* cw = (const float*)d_in[9];
    const float* cb = (const float*)d_in[10];
    float* out = (float*)d_out;

    cudaFuncSetAttribute(proj_kernel, cudaFuncAttributeMaxDynamicSharedMemorySize,
                         PROJ_SMEM_BYTES);
    proj_kernel<<<dim3(3, H_, 5), 512, PROJ_SMEM_BYTES>>>(
        x0, x1, x2, qw, qb, kw, kb, vw, vb);

    size_t smem = (size_t)SMEM_FLOATS * sizeof(float);
    cudaFuncSetAttribute(attn_kernel, cudaFuncAttributeMaxDynamicSharedMemorySize, (int)smem);
    attn_kernel<<<148, NTHR_, smem>>>();

    cudaFuncSetAttribute(outproj_kernel, cudaFuncAttributeMaxDynamicSharedMemorySize,
                         OUTP_SMEM_BYTES);
    outproj_kernel<<<dim3(6, 8), 256, OUTP_SMEM_BYTES>>>(cw, cb, out);
}

// round 16
// speedup vs baseline: 1.2235x; 1.0021x over previous
#include <cuda_runtime.h>
#include <math_constants.h>
#include <stdint.h>

#define B_ 2
#define T_ 192
#define C_ 512
#define H_ 8
#define HS_ 64
#define ORDER_ 3
#define BH_ (B_*H_)

#define NTHR_ 512

// ---- attn smem float offsets ----
#define OFF_K1B  0                      // [192][40] u32 bf16x2 pair-permuted
#define OFF_K2F  7680                   // [192][40] u32 bf16x2 pair-permuted
#define OFF_V2F  15360                  // [64][104] u32 bf16x2 transposed+permuted
#define OFF_V1S  22016                  // [192][72] fp32 (64 data + pad)
#define OFF_YS   35840                  // [2][16][64]
#define OFF_RED  37888                  // [32]
#define OFF_SCR  37920                  // [192][68] staging scratch
#define SMEM_FLOATS 50976               // 203904 B

// ---- proj (bf16): x [128][40] u32 + w [64][40] u32 per buffer, x3 ----
#define PJB_ 40
#define PROJ_BUF_U32  (128*PJB_ + 64*PJB_)          // 7680 u32
#define PROJ_SMEM_BYTES (3 * PROJ_BUF_U32 * 4)      // 92160 B

// ---- outproj (tf32): pair-permuted float2, stride 36 ----
#define PJS_ 36
#define OUTP_BUF_F2   (64*PJS_ + 64*PJS_)
#define OUTP_SMEM_BYTES (3 * OUTP_BUF_F2 * 8)       // 110592 B

#define QSCALE_ (0.125f * 1.4426950408889634f)

// ---- device scratch ----
__device__ float g_Q [BH_*T_*HS_];
__device__ float g_K1[BH_*T_*HS_];
__device__ float g_K2[BH_*T_*HS_];
__device__ float g_V1[BH_*T_*HS_];
__device__ float g_V2[BH_*T_*HS_];
__device__ float g_Y [B_*T_*C_];

typedef unsigned long long u64;

__device__ __forceinline__ uint32_t bf2(float lo, float hi) {
    uint32_t r;
    asm("cvt.rn.bf16x2.f32 %0, %1, %2;" : "=r"(r) : "f"(hi), "f"(lo));
    return r;
}
__device__ __forceinline__ uint32_t mulbf2(uint32_t a, uint32_t b) {
    uint32_t r;
    asm("mul.bf16x2 %0, %1, %2;" : "=r"(r) : "r"(a), "r"(b));
    return r;
}
__device__ __forceinline__ float ex2f(float x) {
    float r;
    asm("ex2.approx.f32 %0, %1;" : "=f"(r) : "f"(x));
    return r;
}
__device__ __forceinline__ float f2tf(float f) {
    uint32_t r;
    asm("cvt.rna.tf32.f32 %0, %1;" : "=r"(r) : "f"(f));
    return __uint_as_float(r);
}
__device__ __forceinline__ void mma_bf16(float* c,
    uint32_t a0, uint32_t a1, uint32_t a2, uint32_t a3,
    uint32_t b0, uint32_t b1)
{
    asm volatile("mma.sync.aligned.m16n8k16.row.col.f32.bf16.bf16.f32 "
        "{%0,%1,%2,%3}, {%4,%5,%6,%7}, {%8,%9}, {%0,%1,%2,%3};"
        : "+f"(c[0]), "+f"(c[1]), "+f"(c[2]), "+f"(c[3])
        : "r"(a0), "r"(a1), "r"(a2), "r"(a3), "r"(b0), "r"(b1));
}
__device__ __forceinline__ void mma_tf32(float* c,
    uint32_t a0, uint32_t a1, uint32_t a2, uint32_t a3,
    uint32_t b0, uint32_t b1)
{
    asm volatile("mma.sync.aligned.m16n8k8.row.col.f32.tf32.tf32.f32 "
        "{%0,%1,%2,%3}, {%4,%5,%6,%7}, {%8,%9}, {%0,%1,%2,%3};"
        : "+f"(c[0]), "+f"(c[1]), "+f"(c[2]), "+f"(c[3])
        : "r"(a0), "r"(a1), "r"(a2), "r"(a3), "r"(b0), "r"(b1));
}
__device__ __forceinline__ float warpSum(float v) {
#pragma unroll
    for (int o = 16; o; o >>= 1) v += __shfl_xor_sync(0xffffffffu, v, o);
    return v;
}

// 16 floats (4 x float4) -> 8 pair-permuted bf16x2 words at dst
__device__ __forceinline__ void store_bf16_pairs(uint32_t* dst,
    float4 e0, float4 e1, float4 e2, float4 e3)
{
    uint32_t p0 = bf2(e0.x, e0.y), p1 = bf2(e0.z, e0.w);
    uint32_t p2 = bf2(e1.x, e1.y), p3 = bf2(e1.z, e1.w);
    uint32_t p4 = bf2(e2.x, e2.y), p5 = bf2(e2.z, e2.w);
    uint32_t p6 = bf2(e3.x, e3.y), p7 = bf2(e3.z, e3.w);
    *(uint4*)(dst)     = make_uint4(p0, p4, p1, p5);
    *(uint4*)(dst + 4) = make_uint4(p2, p6, p3, p7);
}
// convert 8 floats (lo,hi float4 regs) -> 4 pair-permuted tf32 float2 in smem
__device__ __forceinline__ void store_tf32_pairs(float2* d, float4 lo, float4 hi) {
    d[0] = make_float2(f2tf(lo.x), f2tf(hi.x));
    d[1] = make_float2(f2tf(lo.y), f2tf(hi.y));
    d[2] = make_float2(f2tf(lo.z), f2tf(hi.z));
    d[3] = make_float2(f2tf(lo.w), f2tf(hi.w));
}

// =====================================================================
// Kernel 1: per-modality projection as 384x512x512 bf16 GEMM,
// triple-buffered (prefetch distance 2), 512 threads.
// grid (3, 8, 5), block 512.
// =====================================================================
__global__ void __launch_bounds__(512) proj_kernel(
    const float* __restrict__ x0, const float* __restrict__ x1,
    const float* __restrict__ x2,
    const float* __restrict__ qw, const float* __restrict__ qb,
    const float* __restrict__ kw, const float* __restrict__ kb,
    const float* __restrict__ vw, const float* __restrict__ vb)
{
    extern __shared__ uint32_t smu[];

    int rt = blockIdx.x;               // 128-row tile
    int h  = blockIdx.y;               // head == 64-col tile
    int m  = blockIdx.z;

    const float* x; const float* w; const float* bias; float* out; int o;
    switch (m) {
        case 0:  x = x0; w = qw; bias = qb; out = g_Q;  o = 0; break;
        case 1:  x = x1; w = kw; bias = kb; out = g_K1; o = 1; break;
        case 2:  x = x2; w = kw; bias = kb; out = g_K2; o = 2; break;
        case 3:  x = x1; w = vw; bias = vb; out = g_V1; o = 1; break;
        default: x = x2; w = vw; bias = vb; out = g_V2; o = 2; break;
    }
    const float* wrow = w + (size_t)(h*ORDER_ + o)*HS_*C_;
    const float* brow = bias + (h*ORDER_ + o)*HS_;

    int tid = threadIdx.x;
    int lane = tid & 31, wid = tid >> 5;
    int g = lane >> 2, t = lane & 3;
    int mw = wid & 3;     // 32-row warp tile (4)
    int nw = wid >> 2;    // 16-col warp tile (4)

    // staging: one x task per thread (r = tid>>2, kk = tid&3),
    //          one w task for tid < 256 (r = tid>>2, kk = tid&3)
    const float* xsrc;
    int xdst;
    {
        int r = tid >> 2, kk = tid & 3;
        int rg = rt*128 + r;
        int bb = rg >= T_;
        int tt = rg - bb*T_;
        xsrc = x + ((size_t)bb*T_ + tt)*C_ + kk*16;
        xdst = r*PJB_ + kk*8;
    }
    const float* wsrc = nullptr;
    int wdst = 0;
    bool do_w = (tid < 256);
    if (do_w) {
        int r = tid >> 2, kk = tid & 3;
        wsrc = wrow + (size_t)r*C_ + kk*16;
        wdst = 128*PJB_ + r*PJB_ + kk*8;
    }

    float4 px[4], pw[4];
    // prologue: stage chunks 0 and 1 into buffers 0, 1
#pragma unroll
    for (int c = 0; c < 2; ++c) {
        int cc = c * 64;
#pragma unroll
        for (int k = 0; k < 4; ++k) px[k] = *(const float4*)(xsrc + cc + k*4);
        if (do_w) {
#pragma unroll
            for (int k = 0; k < 4; ++k) pw[k] = *(const float4*)(wsrc + cc + k*4);
        }
        uint32_t* buf = smu + c * PROJ_BUF_U32;
        store_bf16_pairs(&buf[xdst], px[0], px[1], px[2], px[3]);
        if (do_w) store_bf16_pairs(&buf[wdst], pw[0], pw[1], pw[2], pw[3]);
    }
    __syncthreads();

    float acc[2][2][4] = {};
    int bufidx = 0;    // = kc % 3
    int wrbuf  = 2;    // = (kc+2) % 3

    for (int kc = 0; kc < 8; ++kc) {
        // prefetch chunk kc+2
        if (kc + 2 < 8) {
            int cc = (kc + 2) * 64;
#pragma unroll
            for (int k = 0; k < 4; ++k) px[k] = *(const float4*)(xsrc + cc + k*4);
            if (do_w) {
#pragma unroll
                for (int k = 0; k < 4; ++k) pw[k] = *(const float4*)(wsrc + cc + k*4);
            }
        }

        const uint32_t* xb = smu + bufidx * PROJ_BUF_U32;
        const uint32_t* wb = xb + 128*PJB_;
#pragma unroll
        for (int kk = 0; kk < 4; ++kk) {
            uint2 bfr[2];
#pragma unroll
            for (int u = 0; u < 2; ++u)
                bfr[u] = *(const uint2*)&wb[(nw*16 + u*8 + g)*PJB_ + kk*8 + 2*t];
#pragma unroll
            for (int s = 0; s < 2; ++s) {
                int row = mw*32 + s*16 + g;
                uint2 alo = *(const uint2*)&xb[row*PJB_ + kk*8 + 2*t];
                uint2 ahi = *(const uint2*)&xb[(row+8)*PJB_ + kk*8 + 2*t];
#pragma unroll
                for (int u = 0; u < 2; ++u)
                    mma_bf16(acc[s][u], alo.x, ahi.x, alo.y, ahi.y,
                             bfr[u].x, bfr[u].y);
            }
        }
        __syncthreads();   // chunk kc consumed by all warps

        if (kc + 2 < 8) {
            uint32_t* buf = smu + wrbuf * PROJ_BUF_U32;   // buffer (kc+2)%3
            store_bf16_pairs(&buf[xdst], px[0], px[1], px[2], px[3]);
            if (do_w) store_bf16_pairs(&buf[wdst], pw[0], pw[1], pw[2], pw[3]);
        }
        bufidx = (bufidx + 1 == 3) ? 0 : bufidx + 1;
        wrbuf  = (wrbuf  + 1 == 3) ? 0 : wrbuf  + 1;
    }

#pragma unroll
    for (int u = 0; u < 2; ++u) {
        int col = nw*16 + u*8 + 2*t;
        float2 bv = *(const float2*)&brow[col];
#pragma unroll
        for (int s = 0; s < 2; ++s) {
#pragma unroll
            for (int half = 0; half < 2; ++half) {
                int rg = rt*128 + mw*32 + s*16 + g + half*8;
                int bb = rg >= T_;
                int tt = rg - bb*T_;
                *(float2*)&out[(size_t)((bb*H_ + h)*T_ + tt)*HS_ + col] =
                    make_float2(acc[s][u][2*half] + bv.x,
                                acc[s][u][2*half+1] + bv.y);
            }
        }
    }
}

// =====================================================================
// Kernel 2: order-3 attention (R15-identical), flat 148-CTA chunking,
// bf16 mma, register-resident P. Fixed-shift softmax (validated R2-R15).
// =====================================================================
__global__ void __launch_bounds__(NTHR_, 1) attn_kernel()
{
    extern __shared__ float sm[];
    uint32_t* K1b = (uint32_t*)(sm + OFF_K1B);  // [192][40]
    uint32_t* K2f = (uint32_t*)(sm + OFF_K2F);  // [192][40]
    uint32_t* V2f = (uint32_t*)(sm + OFF_V2F);  // [64][104]
    float* V1s = sm + OFF_V1S;                  // [192][72]
    float* Ys  = sm + OFF_YS;                   // [2][16][64]
    float* red = sm + OFF_RED;
    float* scr = sm + OFF_SCR;                  // [192][68]

    int cta = blockIdx.x;
    int start  = (cta < 56) ? 22*cta : 20*cta + 112;
    int npairs = (cta < 56) ? 11 : 10;

    int tid  = threadIdx.x;
    int lane = tid & 31, wid = tid >> 5;
    int g = lane >> 2;
    int t = lane & 3;
    int mt = wid & 3;     // 16 j-rows within strip
    int ng = wid >> 2;    // GEMM1 n-block (48) == GEMM2 k-block (48)

    int staged_bh = -1;

    for (int p = 0; p < npairs; ++p) {
        int gq = start + 2*p;
        int bh = gq / T_;
        int i0 = gq - bh*T_;

        if (bh != staged_bh) {
            staged_bh = bh;
            const float* K1g = g_K1 + (size_t)bh*T_*HS_;
            const float* K2g = g_K2 + (size_t)bh*T_*HS_;
            const float* V1g = g_V1 + (size_t)bh*T_*HS_;
            const float* V2g = g_V2 + (size_t)bh*T_*HS_;

            for (int idx = tid; idx < 192*16; idx += NTHR_) {
                int r = idx >> 4, dq = (idx & 15) * 4;
                *(float4*)&scr[r*68 + dq] = ((const float4*)V2g)[idx];
                *(float4*)&V1s[r*72 + dq] = ((const float4*)V1g)[idx];
            }
            for (int task = tid; task < 192*4; task += NTHR_) {
                int r = task >> 2, kk = task & 3;
#pragma unroll
                for (int which = 0; which < 2; ++which) {
                    const float* src = which ? K2g : K1g;
                    uint32_t* dst = (which ? K2f : K1b) + r*40 + kk*8;
                    const float4* s4 = (const float4*)(src + (size_t)r*64 + kk*16);
                    store_bf16_pairs(dst, s4[0], s4[1], s4[2], s4[3]);
                }
            }
            __syncthreads();
            for (int task = tid; task < 64*12; task += NTHR_) {
                int kk = task >> 6, d = task & 63;
                float v[16];
#pragma unroll
                for (int i = 0; i < 16; ++i) v[i] = scr[(kk*16 + i)*68 + d];
                uint32_t pk[8];
#pragma unroll
                for (int mm = 0; mm < 8; ++mm) pk[mm] = bf2(v[2*mm], v[2*mm+1]);
                uint32_t* dst = V2f + d*104 + kk*8;
                *(uint4*)(dst)     = make_uint4(pk[0], pk[4], pk[1], pk[5]);
                *(uint4*)(dst + 4) = make_uint4(pk[2], pk[6], pk[3], pk[7]);
            }
            __syncthreads();
        }

        // ---- q fragments via __ldg (L1 broadcast); scale folds log2(e) ----
        uint32_t qp[2][4][2];
        {
            const float* q0 = g_Q + ((size_t)bh*T_ + i0)*HS_;
#pragma unroll
            for (int q = 0; q < 2; ++q) {
                const float* qr = q0 + q*HS_;
#pragma unroll
                for (int kk = 0; kk < 4; ++kk) {
                    float2 qa = __ldg((const float2*)(qr + kk*16 + 2*t));
                    float2 qb = __ldg((const float2*)(qr + kk*16 + 8 + 2*t));
                    qp[q][kk][0] = bf2(qa.x*QSCALE_, qa.y*QSCALE_);
                    qp[q][kk][1] = bf2(qb.x*QSCALE_, qb.y*QSCALE_);
                }
            }
        }
        float l_run[2] = {0.f, 0.f};
        float yl[2][8][2] = {};

        for (int js = 0; js < 3; ++js) {
            int j0 = js * 64;
            int rowA = j0 + mt*16 + g;

            // ---------------- GEMM1: own 16 j-rows x own 48 k-cols ----------
            float c1[2][6][4] = {};
#pragma unroll
            for (int kk = 0; kk < 4; ++kk) {
                uint2 k1lo = *(const uint2*)&K1b[rowA*40 + kk*8 + 2*t];
                uint2 k1hi = *(const uint2*)&K1b[(rowA+8)*40 + kk*8 + 2*t];
                uint32_t A[2][4];
#pragma unroll
                for (int q = 0; q < 2; ++q) {
                    A[q][0] = mulbf2(k1lo.x, qp[q][kk][0]);
                    A[q][1] = mulbf2(k1hi.x, qp[q][kk][0]);
                    A[q][2] = mulbf2(k1lo.y, qp[q][kk][1]);
                    A[q][3] = mulbf2(k1hi.y, qp[q][kk][1]);
                }
#pragma unroll
                for (int s = 0; s < 6; ++s) {
                    int nrow = ng*48 + s*8 + g;
                    uint2 bb = *(const uint2*)&K2f[nrow*40 + kk*8 + 2*t];
                    mma_bf16(c1[0][s], A[0][0], A[0][1], A[0][2], A[0][3], bb.x, bb.y);
                    mma_bf16(c1[1][s], A[1][0], A[1][1], A[1][2], A[1][3], bb.x, bb.y);
                }
            }

            // --------- exp in registers; C-frags ARE the GEMM2 A-frags ------
            uint32_t a[2][3][4];
#pragma unroll
            for (int q = 0; q < 2; ++q) {
#pragma unroll
                for (int m = 0; m < 3; ++m) {
                    float e00 = ex2f(c1[q][2*m][0]),  e01 = ex2f(c1[q][2*m][1]);
                    float e02 = ex2f(c1[q][2*m][2]),  e03 = ex2f(c1[q][2*m][3]);
                    float e10 = ex2f(c1[q][2*m+1][0]), e11 = ex2f(c1[q][2*m+1][1]);
                    float e12 = ex2f(c1[q][2*m+1][2]), e13 = ex2f(c1[q][2*m+1][3]);
                    l_run[q] += ((e00 + e01) + (e02 + e03))
                              + ((e10 + e11) + (e12 + e13));
                    a[q][m][0] = bf2(e00, e01);
                    a[q][m][1] = bf2(e02, e03);
                    a[q][m][2] = bf2(e10, e11);
                    a[q][m][3] = bf2(e12, e13);
                }
            }

            // ------- GEMM2: k-partial (own 48) x all 64 d; no barrier -------
            int jg0 = j0 + mt*16 + g;
#pragma unroll
            for (int u = 0; u < 8; ++u) {
                float w2[2][4] = {};
#pragma unroll
                for (int m = 0; m < 3; ++m) {
                    uint2 bb = *(const uint2*)&V2f[(u*8 + g)*104 + (ng*3 + m)*8 + 2*t];
                    mma_bf16(w2[0], a[0][m][0], a[0][m][1], a[0][m][2], a[0][m][3], bb.x, bb.y);
                    mma_bf16(w2[1], a[1][m][0], a[1][m][1], a[1][m][2], a[1][m][3], bb.x, bb.y);
                }
                int dc = u*8 + 2*t;
                float2 va = *(const float2*)&V1s[jg0*72 + dc];
                float2 vb = *(const float2*)&V1s[(jg0+8)*72 + dc];
#pragma unroll
                for (int q = 0; q < 2; ++q) {
                    yl[q][u][0] += w2[q][0]*va.x + w2[q][2]*vb.x;
                    yl[q][u][1] += w2[q][1]*va.y + w2[q][3]*vb.y;
                }
            }
        }

        // ---- per-query reductions (sum over g via shfl, then 16 warps) ----
#pragma unroll
        for (int q = 0; q < 2; ++q) {
#pragma unroll
            for (int u = 0; u < 8; ++u)
#pragma unroll
                for (int c = 0; c < 2; ++c) {
                    yl[q][u][c] += __shfl_xor_sync(0xffffffffu, yl[q][u][c], 4);
                    yl[q][u][c] += __shfl_xor_sync(0xffffffffu, yl[q][u][c], 8);
                    yl[q][u][c] += __shfl_xor_sync(0xffffffffu, yl[q][u][c], 16);
                }
            float lw = warpSum(l_run[q]);
            if (lane == 0) red[q*16 + wid] = lw;
            if (lane < 4) {
#pragma unroll
                for (int u = 0; u < 8; ++u) {
                    Ys[q*1024 + wid*64 + u*8 + 2*lane + 0] = yl[q][u][0];
                    Ys[q*1024 + wid*64 + u*8 + 2*lane + 1] = yl[q][u][1];
                }
            }
        }
        __syncthreads();
        if (tid < 128) {
            int q = tid >> 6, c64 = tid & 63;
            float lt = 0.f;
#pragma unroll
            for (int w = 0; w < 16; ++w) lt += red[q*16 + w];
            float y = 0.f;
#pragma unroll
            for (int w = 0; w < 16; ++w) y += Ys[q*1024 + w*64 + c64];
            int b = bh >> 3, h = bh & 7;
            g_Y[((size_t)(b*T_ + i0 + q)*H_ + h)*HS_ + c64] = y / lt;
        }
        __syncthreads();
    }
}

// =====================================================================
// Kernel 3: output projection as 384x512x512 tf32 GEMM, triple-buffered
// (R15-identical). grid (6, 8). block 256.
// =====================================================================
__global__ void __launch_bounds__(256) outproj_kernel(
    const float* __restrict__ cw, const float* __restrict__ cb,
    float* __restrict__ out)
{
    extern __shared__ float2 smp[];

    int rt  = blockIdx.x;              // 64-row tile
    int ct  = blockIdx.y;              // 64-col tile
    int co0 = ct * 64;

    int tid = threadIdx.x;
    int lane = tid & 31, wid = tid >> 5;
    int g = lane >> 2, t = lane & 3;
    int mw = wid & 1;     // 32-row warp tile
    int nw = wid >> 1;    // 16-col warp tile

    const float* xsrc[2];
    int xdst[2];
    const float* wsrc[2];
    int wdst[2];
#pragma unroll
    for (int k = 0; k < 2; ++k) {
        int idx = tid + k*256;
        int r = idx >> 3, sg = idx & 7;
        xsrc[k] = g_Y + (size_t)(rt*64 + r)*C_ + sg*8;
        xdst[k] = r*PJS_ + sg*4;
        wsrc[k] = cw + (size_t)(co0 + r)*C_ + sg*8;
        wdst[k] = 64*PJS_ + r*PJS_ + sg*4;
    }

    float4 pxl[2], pxh[2], pwl[2], pwh[2];
#pragma unroll
    for (int c = 0; c < 2; ++c) {
        int cc = c * 64;
#pragma unroll
        for (int k = 0; k < 2; ++k) {
            pxl[k] = *(const float4*)(xsrc[k] + cc);
            pxh[k] = *(const float4*)(xsrc[k] + cc + 4);
            pwl[k] = *(const float4*)(wsrc[k] + cc);
            pwh[k] = *(const float4*)(wsrc[k] + cc + 4);
        }
        float2* buf = smp + c * OUTP_BUF_F2;
#pragma unroll
        for (int k = 0; k < 2; ++k) {
            store_tf32_pairs(&buf[xdst[k]], pxl[k], pxh[k]);
            store_tf32_pairs(&buf[wdst[k]], pwl[k], pwh[k]);
        }
    }
    __syncthreads();

    float acc[2][2][4] = {};
    int bufidx = 0;    // = kc % 3
    int wrbuf  = 2;    // = (kc+2) % 3

    for (int kc = 0; kc < 8; ++kc) {
        if (kc + 2 < 8) {
            int cc = (kc + 2) * 64;
#pragma unroll
            for (int k = 0; k < 2; ++k) {
                pxl[k] = *(const float4*)(xsrc[k] + cc);
                pxh[k] = *(const float4*)(xsrc[k] + cc + 4);
                pwl[k] = *(const float4*)(wsrc[k] + cc);
                pwh[k] = *(const float4*)(wsrc[k] + cc + 4);
            }
        }

        const float2* xsP = smp + bufidx * OUTP_BUF_F2;
        const float2* wsP = xsP + 64*PJS_;
#pragma unroll
        for (int kk = 0; kk < 8; ++kk) {
            uint32_t b0[2], b1[2];
#pragma unroll
            for (int u = 0; u < 2; ++u) {
                float2 bb = wsP[(nw*16 + u*8 + g)*PJS_ + kk*4 + t];
                b0[u] = __float_as_uint(bb.x);
                b1[u] = __float_as_uint(bb.y);
            }
#pragma unroll
            for (int s = 0; s < 2; ++s) {
                int row = mw*32 + s*16 + g;
                float2 a02 = xsP[row*PJS_ + kk*4 + t];
                float2 a13 = xsP[(row+8)*PJS_ + kk*4 + t];
#pragma unroll
                for (int u = 0; u < 2; ++u)
                    mma_tf32(acc[s][u],
                        __float_as_uint(a02.x), __float_as_uint(a13.x),
                        __float_as_uint(a02.y), __float_as_uint(a13.y),
                        b0[u], b1[u]);
            }
        }
        __syncthreads();

        if (kc + 2 < 8) {
            float2* buf = smp + wrbuf * OUTP_BUF_F2;   // buffer (kc+2)%3
#pragma unroll
            for (int k = 0; k < 2; ++k) {
                store_tf32_pairs(&buf[xdst[k]], pxl[k], pxh[k]);
                store_tf32_pairs(&buf[wdst[k]], pwl[k], pwh[k]);
            }
        }
        bufidx = (bufidx + 1 == 3) ? 0 : bufidx + 1;
        wrbuf  = (wrbuf  + 1 == 3) ? 0 : wrbuf  + 1;
    }

#pragma unroll
    for (int u = 0; u < 2; ++u) {
        int col = co0 + nw*16 + u*8 + 2*t;
        float2 bv = *(const float2*)&cb[col];
#pragma unroll
        for (int s = 0; s < 2; ++s) {
            int rg = rt*64 + mw*32 + s*16 + g;
            *(float2*)&out[(size_t)rg*C_ + col] =
                make_float2(acc[s][u][0] + bv.x, acc[s][u][1] + bv.y);
            *(float2*)&out[(size_t)(rg+8)*C_ + col] =
                make_float2(acc[s][u][2] + bv.x, acc[s][u][3] + bv.y);
        }
    }
}

// =====================================================================
extern "C" void kernel_launch(void* const* d_in, const int* in_sizes, int n_in,
                              void* d_out, int out_size)
{
    const float* x0 = (const float*)d_in[0];
    const float* x1 = (const float*)d_in[1];
    const float* x2 = (const float*)d_in[2];
    const float* qw = (const float*)d_in[3];
    const float* qb = (const float*)d_in[4];
    const float* kw = (const float*)d_in[5];
    const float* kb = (const float*)d_in[6];
    const float* vw = (const float*)d_in[7];
    const float* vb = (const float*)d_in[8];
    const float* cw = (const float*)d_in[9];
    const float* cb = (const float*)d_in[10];
    float* out = (float*)d_out;

    cudaFuncSetAttribute(proj_kernel, cudaFuncAttributeMaxDynamicSharedMemorySize,
                         PROJ_SMEM_BYTES);
    proj_kernel<<<dim3(3, H_, 5), 512, PROJ_SMEM_BYTES>>>(
        x0, x1, x2, qw, qb, kw, kb, vw, vb);

    size_t smem = (size_t)SMEM_FLOATS * sizeof(float);
    cudaFuncSetAttribute(attn_kernel, cudaFuncAttributeMaxDynamicSharedMemorySize, (int)smem);
    attn_kernel<<<148, NTHR_, smem>>>();

    cudaFuncSetAttribute(outproj_kernel, cudaFuncAttributeMaxDynamicSharedMemorySize,
                         OUTP_SMEM_BYTES);
    outproj_kernel<<<dim3(6, 8), 256, OUTP_SMEM_BYTES>>>(cw, cb, out);
}